// round 11
// baseline (speedup 1.0000x reference)
#include <cuda_runtime.h>
#include <cuda_fp16.h>
#include <math.h>
#include <stdint.h>

// Problem constants
#define B_  4
#define L_  4096
#define E_  512
#define H_  16
#define ML  (B_*L_)            // 16384 tokens
#define EPS_ 1e-6f
#define SC_  16384.0f          // z/U scale split (keeps fp16 ranges normal)

// ---------------------------------------------------------------------------
// Scratch (static __device__ arrays; no allocation anywhere)
// ---------------------------------------------------------------------------
__device__ float g_Q[ML*E_];   // elu(q)+1
__device__ float g_K[ML*E_];   // elu(k)+1
__device__ float g_V[ML*E_];   // v projection (unscaled; /L * L cancels exactly)
__device__ __half g_Wh[3*E_*E_];  // Wq,Wk,Wv as fp16
__device__ __half g_Uh[B_*E_*E_]; // per-batch fused KV@Wm^T (scaled 1/SC_)
__device__ float g_Z[ML*H_];      // SC_ / (Q.Ksum + eps)

#define NCHUNK 32
#define KV_ELEMS   (B_*H_*32*32)     // 65536
#define KSUM_ELEMS (B_*H_*32)        // 2048
#define PART_STRIDE (KV_ELEMS + KSUM_ELEMS)   // 67584
__device__ float g_part[NCHUNK * PART_STRIDE];
__device__ float g_KV[KV_ELEMS];
__device__ float g_Ksum[KSUM_ELEMS];

// ---------------------------------------------------------------------------
// PTX helpers: ldmatrix + fp16 mma (fp32 accumulate)
// ---------------------------------------------------------------------------
__device__ __forceinline__ unsigned smem_u32(const void* p) {
    return (unsigned)__cvta_generic_to_shared(p);
}
__device__ __forceinline__ void ldsm_x4(unsigned* r, unsigned addr) {
    asm volatile("ldmatrix.sync.aligned.m8n8.x4.shared.b16 {%0,%1,%2,%3}, [%4];"
                 : "=r"(r[0]), "=r"(r[1]), "=r"(r[2]), "=r"(r[3]) : "r"(addr));
}
__device__ __forceinline__ void mma_f16(float* c, const unsigned* a, const unsigned* b) {
    asm volatile("mma.sync.aligned.m16n8k16.row.col.f32.f16.f16.f32 "
                 "{%0,%1,%2,%3}, {%4,%5,%6,%7}, {%8,%9}, {%0,%1,%2,%3};"
                 : "+f"(c[0]), "+f"(c[1]), "+f"(c[2]), "+f"(c[3])
                 : "r"(a[0]), "r"(a[1]), "r"(a[2]), "r"(a[3]),
                   "r"(b[0]), "r"(b[1]));
}

// 8 fp32 -> fp16 hi (rn) + fp16 lo (exact residual, rn): ~22 mantissa bits
__device__ __forceinline__ void cvt8_split(const float* __restrict__ v8,
                                           uint4& h, uint4& l) {
    uint32_t hp[4], lp[4];
    #pragma unroll
    for (int i = 0; i < 4; i++) {
        float x0 = v8[2*i], x1 = v8[2*i+1];
        __half2 hh = __floats2half2_rn(x0, x1);
        float2 hf = __half22float2(hh);
        __half2 ll = __floats2half2_rn(x0 - hf.x, x1 - hf.y);
        hp[i] = *(uint32_t*)&hh;
        lp[i] = *(uint32_t*)&ll;
    }
    h = make_uint4(hp[0], hp[1], hp[2], hp[3]);
    l = make_uint4(lp[0], lp[1], lp[2], lp[3]);
}

// ---------------------------------------------------------------------------
// Weight pre-convert: fp32 -> fp16, 3 matrices (Wq, Wk, Wv)
// ---------------------------------------------------------------------------
__global__ void wcvt(const float* __restrict__ W0, const float* __restrict__ W1,
                     const float* __restrict__ W2, __half* __restrict__ out)
{
    const int z = blockIdx.y;
    const float* src = (z == 0) ? W0 : (z == 1 ? W1 : W2);
    int i = (blockIdx.x * 256 + threadIdx.x) * 4;
    float4 v = *(const float4*)(src + i);
    __half2 a = __floats2half2_rn(v.x, v.y);
    __half2 b = __floats2half2_rn(v.z, v.w);
    uint2 pk = make_uint2(*(uint32_t*)&a, *(uint32_t*)&b);
    *(uint2*)(out + (size_t)z * E_ * E_ + i) = pk;
}

// ---------------------------------------------------------------------------
// GEMM: C[M,N] = A[M,K] @ W[N,K]^T, fp32 A (fp16x2 split in staging),
// fp16 W (pre-converted -> B staging is a pure copy), fp32 out.
//   C = Ahi*W + Alo*W
// Block 128x128, k-tile 32, 8 warps, warp tile 32x64, mma.m16n8k16,
// smem row stride 40 halves (conflict-free ldmatrix), register prefetch,
// single buffer + two barriers (measured-best schedule), 2 CTAs/SM.
// Optional Zs: per-(row, k-tile) scale folded into A staging (heads are
// 32-wide = exactly one head per k-tile). Optional per-batch W advance.
// ---------------------------------------------------------------------------
struct GemmArgs {
    const float* A[3]; const __half* W[3]; float* C[3];
    const float* Zs;    // null = no scaling; else Zs[row*16 + ktile]
    int actmask;
    int wPerBatch;      // W += 512*512 per 4096 A-rows
};

__global__ __launch_bounds__(256, 2)
void gemm_f16x2(GemmArgs args)
{
    const int z = blockIdx.z;
    const float* A = args.A[z];
    float*       C = args.C[z];
    const bool act = (args.actmask >> z) & 1;

    const int m0 = blockIdx.y * 128;
    const int n0 = blockIdx.x * 128;

    const __half* Wb = args.W[z];
    if (args.wPerBatch) Wb += (size_t)(m0 >> 12) * (E_ * E_);

    __shared__ __half sAh[128 * 40];
    __shared__ __half sAl[128 * 40];
    __shared__ __half sB [128 * 40];

    const int tid  = threadIdx.x;
    const int lane = tid & 31;
    const int warp = tid >> 5;
    const int wm0 = (warp & 3) * 32;     // warp row origin in tile
    const int wn0 = (warp >> 2) * 64;    // warp col origin in tile

    // global-load mapping: each thread owns one 16-elem row segment
    const int lrow = tid >> 1;           // 0..127
    const int lkc  = (tid & 1) * 16;     // k offset 0 or 16

    const float*  gA = A  + (size_t)(m0 + lrow) * 512 + lkc;
    const __half* gB = Wb + (size_t)(n0 + lrow) * 512 + lkc;
    const float*  Zrow = args.Zs ? (args.Zs + (size_t)(m0 + lrow) * 16) : nullptr;

    float acc[2][8][4];
    #pragma unroll
    for (int i = 0; i < 2; i++)
        #pragma unroll
        for (int j = 0; j < 8; j++)
            #pragma unroll
            for (int t = 0; t < 4; t++) acc[i][j][t] = 0.0f;

    const int sA0 = lrow * 40 + lkc;

    // ---- prologue: tile 0 ----
    float4 ra[4]; uint4 rb0, rb1; float zc;
    #pragma unroll
    for (int i = 0; i < 4; i++) ra[i] = *(const float4*)(gA + 4 * i);
    rb0 = *(const uint4*)(gB);
    rb1 = *(const uint4*)(gB + 8);
    zc = Zrow ? Zrow[0] : 1.0f;
    {
        if (Zrow) {
            #pragma unroll
            for (int i = 0; i < 4; i++) {
                ra[i].x *= zc; ra[i].y *= zc; ra[i].z *= zc; ra[i].w *= zc;
            }
        }
        uint4 h0, l0, h1, l1;
        cvt8_split((const float*)&ra[0], h0, l0);
        cvt8_split((const float*)&ra[2], h1, l1);
        *(uint4*)&sAh[sA0] = h0; *(uint4*)&sAh[sA0 + 8] = h1;
        *(uint4*)&sAl[sA0] = l0; *(uint4*)&sAl[sA0 + 8] = l1;
        *(uint4*)&sB[sA0] = rb0; *(uint4*)&sB[sA0 + 8] = rb1;
    }
    __syncthreads();

    // ldmatrix address components
    const int a_r = lane & 15;              // row within m16 tile
    const int a_c = (lane >> 4) * 8;        // col half
    const int b_r = lane & 7;               // row within n8 tile
    const int b_nt = (lane >> 4) & 1;       // which of 2 n-tiles in x4
    const int b_c = ((lane >> 3) & 1) * 8;  // col half

    for (int kt = 0; kt < 16; ++kt) {
        if (kt < 15) {
            const int ko = (kt + 1) * 32;
            #pragma unroll
            for (int i = 0; i < 4; i++) ra[i] = *(const float4*)(gA + ko + 4 * i);
            rb0 = *(const uint4*)(gB + ko);
            rb1 = *(const uint4*)(gB + ko + 8);
            zc = Zrow ? Zrow[kt + 1] : 1.0f;
        }

        #pragma unroll
        for (int ks = 0; ks < 2; ks++) {
            const int kk = ks * 16;
            unsigned ah[2][4], al[2][4];
            ldsm_x4(ah[0], smem_u32(&sAh[(wm0 + a_r) * 40 + kk + a_c]));
            ldsm_x4(ah[1], smem_u32(&sAh[(wm0 + 16 + a_r) * 40 + kk + a_c]));
            ldsm_x4(al[0], smem_u32(&sAl[(wm0 + a_r) * 40 + kk + a_c]));
            ldsm_x4(al[1], smem_u32(&sAl[(wm0 + 16 + a_r) * 40 + kk + a_c]));

            #pragma unroll
            for (int ntp = 0; ntp < 4; ntp++) {
                unsigned b[4];
                const int brow = wn0 + ntp * 16 + b_nt * 8 + b_r;
                ldsm_x4(b, smem_u32(&sB[brow * 40 + kk + b_c]));
                #pragma unroll
                for (int half = 0; half < 2; half++) {
                    const int nt = ntp * 2 + half;
                    const unsigned* bp = b + 2 * half;
                    mma_f16(acc[0][nt], ah[0], bp);
                    mma_f16(acc[0][nt], al[0], bp);
                    mma_f16(acc[1][nt], ah[1], bp);
                    mma_f16(acc[1][nt], al[1], bp);
                }
            }
        }

        if (kt < 15) {
            __syncthreads();
            if (Zrow) {
                #pragma unroll
                for (int i = 0; i < 4; i++) {
                    ra[i].x *= zc; ra[i].y *= zc; ra[i].z *= zc; ra[i].w *= zc;
                }
            }
            uint4 h0, l0, h1, l1;
            cvt8_split((const float*)&ra[0], h0, l0);
            cvt8_split((const float*)&ra[2], h1, l1);
            *(uint4*)&sAh[sA0] = h0; *(uint4*)&sAh[sA0 + 8] = h1;
            *(uint4*)&sAl[sA0] = l0; *(uint4*)&sAl[sA0 + 8] = l1;
            *(uint4*)&sB[sA0] = rb0; *(uint4*)&sB[sA0 + 8] = rb1;
            __syncthreads();
        }
    }

    // ---- epilogue: optional elu(x)+1 (= x+1 if x>0 else exp(x)), fp32 out ----
    const int row0 = m0 + wm0 + (lane >> 2);
    const int col0 = n0 + wn0 + (lane & 3) * 2;
    #pragma unroll
    for (int mt = 0; mt < 2; mt++) {
        #pragma unroll
        for (int nt = 0; nt < 8; nt++) {
            float c0 = acc[mt][nt][0], c1 = acc[mt][nt][1];
            float c2 = acc[mt][nt][2], c3 = acc[mt][nt][3];
            if (act) {
                c0 = (c0 > 0.0f) ? (c0 + 1.0f) : expf(c0);
                c1 = (c1 > 0.0f) ? (c1 + 1.0f) : expf(c1);
                c2 = (c2 > 0.0f) ? (c2 + 1.0f) : expf(c2);
                c3 = (c3 > 0.0f) ? (c3 + 1.0f) : expf(c3);
            }
            const int r = row0 + mt * 16;
            const int cc = col0 + nt * 8;
            *(float2*)(C + (size_t)r * 512 + cc)       = make_float2(c0, c1);
            *(float2*)(C + (size_t)(r + 8) * 512 + cc) = make_float2(c2, c3);
        }
    }
}

// ---------------------------------------------------------------------------
// Stage 2a: per-(s-chunk, b, h) partial KV[d][dv] and Ksum[d]. Deterministic.
// ---------------------------------------------------------------------------
__global__ void kv_partial(const float* __restrict__ Kf,
                           const float* __restrict__ Vf,
                           float* __restrict__ part)
{
    const int c  = blockIdx.x;
    const int bh = blockIdx.y;
    const int b  = bh >> 4;
    const int h  = bh & 15;
    const int tid = threadIdx.x;

    __shared__ __align__(16) float Ks[8][32];
    __shared__ __align__(16) float Vs[8][32];

    const int d   = tid >> 3;
    const int dv0 = (tid & 7) << 2;
    const int lr  = tid >> 5;   // 0..7
    const int lc  = tid & 31;

    const size_t base = ((size_t)(b * L_ + c * (L_ / NCHUNK)) * 512) + h * 32;
    const float* Kb = Kf + base;
    const float* Vb = Vf + base;

    float a0 = 0.f, a1 = 0.f, a2 = 0.f, a3 = 0.f, ks = 0.f;

    for (int s = 0; s < L_ / NCHUNK; s += 8) {
        Ks[lr][lc] = Kb[(size_t)(s + lr) * 512 + lc];
        Vs[lr][lc] = Vb[(size_t)(s + lr) * 512 + lc];
        __syncthreads();
        #pragma unroll
        for (int u = 0; u < 8; u++) {
            float kd = Ks[u][d];
            float4 vv = *(const float4*)&Vs[u][dv0];
            a0 += kd * vv.x; a1 += kd * vv.y;
            a2 += kd * vv.z; a3 += kd * vv.w;
            ks += kd;
        }
        __syncthreads();
    }

    float* p = part + (size_t)c * PART_STRIDE;
    const int o = bh * 1024 + d * 32 + dv0;
    p[o + 0] = a0; p[o + 1] = a1; p[o + 2] = a2; p[o + 3] = a3;
    if ((tid & 7) == 0) p[KV_ELEMS + bh * 32 + d] = ks;
}

// Stage 2b: reduce NCHUNK partials -> g_KV, g_Ksum (deterministic order)
__global__ void kv_reduce(const float* __restrict__ part,
                          float* __restrict__ KV,
                          float* __restrict__ Ksum)
{
    const int i = blockIdx.x * 256 + threadIdx.x;
    if (i >= PART_STRIDE) return;
    float s = 0.f;
    #pragma unroll
    for (int c = 0; c < NCHUNK; c++) s += part[(size_t)c * PART_STRIDE + i];
    if (i < KV_ELEMS) KV[i] = s;
    else              Ksum[i - KV_ELEMS] = s;
}

// ---------------------------------------------------------------------------
// Z kernel: Z[l,h] = SC_ / (Q[l,h,:].Ksum[b,h] + eps). One thread per (l,h);
// each thread reads a 128B Q segment (coalesced across threads).
// ---------------------------------------------------------------------------
__global__ __launch_bounds__(256)
void zker(const float* __restrict__ Q, const float* __restrict__ Ksum,
          float* __restrict__ Z)
{
    const int idx = blockIdx.x * 256 + threadIdx.x;   // 0 .. ML*16-1
    const int l = idx >> 4, h = idx & 15;
    const int b = l >> 12;
    const float* Qp = Q + (size_t)l * 512 + h * 32;
    const float* Kp = Ksum + (b * 16 + h) * 32;
    float den = 0.f;
    #pragma unroll
    for (int d = 0; d < 32; d += 4) {
        float4 q4 = *(const float4*)(Qp + d);
        den += q4.x * Kp[d] + q4.y * Kp[d+1] + q4.z * Kp[d+2] + q4.w * Kp[d+3];
    }
    Z[idx] = SC_ / (den + EPS_);
}

// ---------------------------------------------------------------------------
// U build: U[b][e][32h+d] = (1/SC_) * sum_dv KV[b,h,d,dv] * Wm[e, 32h+dv]
// One block per (b,h); KV tile in smem; 67 MFLOP total.
// ---------------------------------------------------------------------------
__global__ __launch_bounds__(256)
void ubuild(const float* __restrict__ KV, const float* __restrict__ Wm,
            __half* __restrict__ U)
{
    const int bh = blockIdx.x;
    const int b = bh >> 4, h = bh & 15;
    const int tid = threadIdx.x;

    __shared__ __align__(16) float KVs[1024];
    for (int i = tid; i < 1024; i += 256) KVs[i] = KV[(size_t)bh * 1024 + i];
    __syncthreads();

    const int d0 = (tid & 7) * 4;
    for (int e0 = 0; e0 < 512; e0 += 32) {
        const int e = e0 + (tid >> 3);
        const float* wrow = Wm + (size_t)e * 512 + h * 32;
        float a0 = 0.f, a1 = 0.f, a2 = 0.f, a3 = 0.f;
        #pragma unroll 8
        for (int dv = 0; dv < 32; dv++) {
            float wv = wrow[dv];
            a0 += KVs[(d0 + 0) * 32 + dv] * wv;
            a1 += KVs[(d0 + 1) * 32 + dv] * wv;
            a2 += KVs[(d0 + 2) * 32 + dv] * wv;
            a3 += KVs[(d0 + 3) * 32 + dv] * wv;
        }
        const float is = 1.0f / SC_;
        __half2 p0 = __floats2half2_rn(a0 * is, a1 * is);
        __half2 p1 = __floats2half2_rn(a2 * is, a3 * is);
        __half* dst = U + ((size_t)b * 512 + e) * 512 + h * 32 + d0;
        *(__half2*)(dst)     = p0;
        *(__half2*)(dst + 2) = p1;
    }
}

// ---------------------------------------------------------------------------
// Launch. Inputs (metadata order): query, key, value, Wq, Wk, Wv, Wm. f32 out.
// ---------------------------------------------------------------------------
extern "C" void kernel_launch(void* const* d_in, const int* in_sizes, int n_in,
                              void* d_out, int out_size)
{
    (void)in_sizes; (void)n_in; (void)out_size;
    const float* q  = (const float*)d_in[0];
    const float* k  = (const float*)d_in[1];
    const float* v  = (const float*)d_in[2];
    const float* Wq = (const float*)d_in[3];
    const float* Wk = (const float*)d_in[4];
    const float* Wv = (const float*)d_in[5];
    const float* Wm = (const float*)d_in[6];
    float* out = (float*)d_out;

    float *gQ, *gK, *gV, *gPart, *gKV, *gKs, *gZ;
    __half *gWh, *gUh;
    cudaGetSymbolAddress((void**)&gQ,    g_Q);
    cudaGetSymbolAddress((void**)&gK,    g_K);
    cudaGetSymbolAddress((void**)&gV,    g_V);
    cudaGetSymbolAddress((void**)&gPart, g_part);
    cudaGetSymbolAddress((void**)&gKV,   g_KV);
    cudaGetSymbolAddress((void**)&gKs,   g_Ksum);
    cudaGetSymbolAddress((void**)&gZ,    g_Z);
    cudaGetSymbolAddress((void**)&gWh,   g_Wh);
    cudaGetSymbolAddress((void**)&gUh,   g_Uh);

    const int EE = E_ * E_;

    // 0) weights -> fp16 (once)
    wcvt<<<dim3(EE / 4 / 256, 3), 256>>>(Wq, Wk, Wv, gWh);

    // 1) fused projections: q,k -> elu+1 ; v -> raw
    {
        GemmArgs a;
        a.A[0] = q; a.W[0] = gWh + 0 * EE; a.C[0] = gQ;
        a.A[1] = k; a.W[1] = gWh + 1 * EE; a.C[1] = gK;
        a.A[2] = v; a.W[2] = gWh + 2 * EE; a.C[2] = gV;
        a.Zs = nullptr; a.actmask = 0x3; a.wPerBatch = 0;
        gemm_f16x2<<<dim3(4, 128, 3), 256>>>(a);
    }

    // 2) KV + Ksum (deterministic two-phase reduction)
    kv_partial<<<dim3(NCHUNK, B_ * H_), 256>>>(gK, gV, gPart);
    kv_reduce<<<(PART_STRIDE + 255) / 256, 256>>>(gPart, gKV, gKs);

    // 3) Z and fused U = KV @ Wm_head^T (per batch)
    zker<<<ML * H_ / 256, 256>>>(gQ, gKs, gZ);
    ubuild<<<B_ * H_, 256>>>(gKV, Wm, gUh);

    // 4) fused message+merge GEMM: out = (Z*Q) @ U_b^T
    {
        GemmArgs a;
        a.A[0] = gQ; a.W[0] = gUh; a.C[0] = out;
        a.A[1] = gQ; a.W[1] = gUh; a.C[1] = out;
        a.A[2] = gQ; a.W[2] = gUh; a.C[2] = out;
        a.Zs = gZ; a.actmask = 0; a.wPerBatch = 1;
        gemm_f16x2<<<dim3(4, 128, 1), 256>>>(a);
    }
}

// round 12
// speedup vs baseline: 1.2583x; 1.2583x over previous
#include <cuda_runtime.h>
#include <cuda_fp16.h>
#include <math.h>
#include <stdint.h>

// Problem constants
#define B_  4
#define L_  4096
#define E_  512
#define H_  16
#define ML  (B_*L_)            // 16384 tokens
#define EPS_ 1e-6f
#define SC_  16384.0f          // z/U scale split (keeps fp16 ranges normal)

// ---------------------------------------------------------------------------
// Scratch (static __device__ arrays; no allocation anywhere)
// ---------------------------------------------------------------------------
__device__ float g_Q[ML*E_];   // elu(q)+1
__device__ float g_K[ML*E_];   // elu(k)+1
__device__ float g_V[ML*E_];   // v projection (unscaled; /L * L cancels exactly)
__device__ __half g_Wh[3*E_*E_];  // Wq,Wk,Wv as fp16
__device__ __half g_Uh[B_*E_*E_]; // per-batch fused KV@Wm^T (scaled 1/SC_)
__device__ float g_Z[ML*H_];      // SC_ / (Q.Ksum + eps)

#define NCHUNK 32
#define KV_ELEMS   (B_*H_*32*32)     // 65536
#define KSUM_ELEMS (B_*H_*32)        // 2048
#define PART_STRIDE (KV_ELEMS + KSUM_ELEMS)   // 67584
__device__ float g_part[NCHUNK * PART_STRIDE];
__device__ float g_KV[KV_ELEMS];
__device__ float g_Ksum[KSUM_ELEMS];

// ---------------------------------------------------------------------------
// PTX helpers: ldmatrix + fp16 mma (fp32 accumulate)
// ---------------------------------------------------------------------------
__device__ __forceinline__ unsigned smem_u32(const void* p) {
    return (unsigned)__cvta_generic_to_shared(p);
}
__device__ __forceinline__ void ldsm_x4(unsigned* r, unsigned addr) {
    asm volatile("ldmatrix.sync.aligned.m8n8.x4.shared.b16 {%0,%1,%2,%3}, [%4];"
                 : "=r"(r[0]), "=r"(r[1]), "=r"(r[2]), "=r"(r[3]) : "r"(addr));
}
__device__ __forceinline__ void mma_f16(float* c, const unsigned* a, const unsigned* b) {
    asm volatile("mma.sync.aligned.m16n8k16.row.col.f32.f16.f16.f32 "
                 "{%0,%1,%2,%3}, {%4,%5,%6,%7}, {%8,%9}, {%0,%1,%2,%3};"
                 : "+f"(c[0]), "+f"(c[1]), "+f"(c[2]), "+f"(c[3])
                 : "r"(a[0]), "r"(a[1]), "r"(a[2]), "r"(a[3]),
                   "r"(b[0]), "r"(b[1]));
}

// 8 fp32 (optionally scaled) -> packed fp16 rn
__device__ __forceinline__ void cvt8_h(const float* __restrict__ v8, float s,
                                       uint4& h) {
    uint32_t hp[4];
    #pragma unroll
    for (int i = 0; i < 4; i++) {
        __half2 hh = __floats2half2_rn(v8[2*i] * s, v8[2*i+1] * s);
        hp[i] = *(uint32_t*)&hh;
    }
    h = make_uint4(hp[0], hp[1], hp[2], hp[3]);
}

// ---------------------------------------------------------------------------
// Weight pre-convert: fp32 -> fp16, 3 matrices (Wq, Wk, Wv)
// ---------------------------------------------------------------------------
__global__ void wcvt(const float* __restrict__ W0, const float* __restrict__ W1,
                     const float* __restrict__ W2, __half* __restrict__ out)
{
    const int z = blockIdx.y;
    const float* src = (z == 0) ? W0 : (z == 1 ? W1 : W2);
    int i = (blockIdx.x * 256 + threadIdx.x) * 4;
    float4 v = *(const float4*)(src + i);
    __half2 a = __floats2half2_rn(v.x, v.y);
    __half2 b = __floats2half2_rn(v.z, v.w);
    uint2 pk = make_uint2(*(uint32_t*)&a, *(uint32_t*)&b);
    *(uint2*)(out + (size_t)z * E_ * E_ + i) = pk;
}

// ---------------------------------------------------------------------------
// GEMM: C[M,N] = A[M,K] @ W[N,K]^T, single-term fp16 (A rn-quantized in
// staging, W pre-converted fp16 -> B staging is a pure copy), fp32 accum/out.
// Block 128x128, k-tile 32, 8 warps, warp tile 32x64, mma.m16n8k16,
// smem row stride 40 halves (conflict-free ldmatrix), register prefetch,
// single buffer + two barriers (measured-best schedule), 2 CTAs/SM.
// Optional Zs: per-(row, k-tile) scale folded into A staging (heads are
// 32-wide = exactly one head per k-tile). Optional per-batch W advance.
// ---------------------------------------------------------------------------
struct GemmArgs {
    const float* A[3]; const __half* W[3]; float* C[3];
    const float* Zs;    // null = no scaling; else Zs[row*16 + ktile]
    int actmask;
    int wPerBatch;      // W += 512*512 per 4096 A-rows
};

__global__ __launch_bounds__(256, 2)
void gemm_f16(GemmArgs args)
{
    const int z = blockIdx.z;
    const float* A = args.A[z];
    float*       C = args.C[z];
    const bool act = (args.actmask >> z) & 1;

    const int m0 = blockIdx.y * 128;
    const int n0 = blockIdx.x * 128;

    const __half* Wb = args.W[z];
    if (args.wPerBatch) Wb += (size_t)(m0 >> 12) * (E_ * E_);

    __shared__ __half sAh[128 * 40];
    __shared__ __half sB [128 * 40];

    const int tid  = threadIdx.x;
    const int lane = tid & 31;
    const int warp = tid >> 5;
    const int wm0 = (warp & 3) * 32;     // warp row origin in tile
    const int wn0 = (warp >> 2) * 64;    // warp col origin in tile

    // global-load mapping: each thread owns one 16-elem row segment
    const int lrow = tid >> 1;           // 0..127
    const int lkc  = (tid & 1) * 16;     // k offset 0 or 16

    const float*  gA = A  + (size_t)(m0 + lrow) * 512 + lkc;
    const __half* gB = Wb + (size_t)(n0 + lrow) * 512 + lkc;
    const float*  Zrow = args.Zs ? (args.Zs + (size_t)(m0 + lrow) * 16) : nullptr;

    float acc[2][8][4];
    #pragma unroll
    for (int i = 0; i < 2; i++)
        #pragma unroll
        for (int j = 0; j < 8; j++)
            #pragma unroll
            for (int t = 0; t < 4; t++) acc[i][j][t] = 0.0f;

    const int sA0 = lrow * 40 + lkc;

    // ---- prologue: tile 0 ----
    float4 ra[4]; uint4 rb0, rb1; float zc;
    #pragma unroll
    for (int i = 0; i < 4; i++) ra[i] = *(const float4*)(gA + 4 * i);
    rb0 = *(const uint4*)(gB);
    rb1 = *(const uint4*)(gB + 8);
    zc = Zrow ? Zrow[0] : 1.0f;
    {
        uint4 h0, h1;
        cvt8_h((const float*)&ra[0], zc, h0);
        cvt8_h((const float*)&ra[2], zc, h1);
        *(uint4*)&sAh[sA0] = h0; *(uint4*)&sAh[sA0 + 8] = h1;
        *(uint4*)&sB[sA0] = rb0; *(uint4*)&sB[sA0 + 8] = rb1;
    }
    __syncthreads();

    // ldmatrix address components
    const int a_r = lane & 15;              // row within m16 tile
    const int a_c = (lane >> 4) * 8;        // col half
    const int b_r = lane & 7;               // row within n8 tile
    const int b_nt = (lane >> 4) & 1;       // which of 2 n-tiles in x4
    const int b_c = ((lane >> 3) & 1) * 8;  // col half

    for (int kt = 0; kt < 16; ++kt) {
        if (kt < 15) {
            const int ko = (kt + 1) * 32;
            #pragma unroll
            for (int i = 0; i < 4; i++) ra[i] = *(const float4*)(gA + ko + 4 * i);
            rb0 = *(const uint4*)(gB + ko);
            rb1 = *(const uint4*)(gB + ko + 8);
            zc = Zrow ? Zrow[kt + 1] : 1.0f;
        }

        #pragma unroll
        for (int ks = 0; ks < 2; ks++) {
            const int kk = ks * 16;
            unsigned ah[2][4];
            ldsm_x4(ah[0], smem_u32(&sAh[(wm0 + a_r) * 40 + kk + a_c]));
            ldsm_x4(ah[1], smem_u32(&sAh[(wm0 + 16 + a_r) * 40 + kk + a_c]));

            #pragma unroll
            for (int ntp = 0; ntp < 4; ntp++) {
                unsigned b[4];
                const int brow = wn0 + ntp * 16 + b_nt * 8 + b_r;
                ldsm_x4(b, smem_u32(&sB[brow * 40 + kk + b_c]));
                #pragma unroll
                for (int half = 0; half < 2; half++) {
                    const int nt = ntp * 2 + half;
                    const unsigned* bp = b + 2 * half;
                    mma_f16(acc[0][nt], ah[0], bp);
                    mma_f16(acc[1][nt], ah[1], bp);
                }
            }
        }

        if (kt < 15) {
            __syncthreads();
            uint4 h0, h1;
            cvt8_h((const float*)&ra[0], zc, h0);
            cvt8_h((const float*)&ra[2], zc, h1);
            *(uint4*)&sAh[sA0] = h0; *(uint4*)&sAh[sA0 + 8] = h1;
            *(uint4*)&sB[sA0] = rb0; *(uint4*)&sB[sA0 + 8] = rb1;
            __syncthreads();
        }
    }

    // ---- epilogue: optional elu(x)+1 (= x+1 if x>0 else exp(x)), fp32 out ----
    const int row0 = m0 + wm0 + (lane >> 2);
    const int col0 = n0 + wn0 + (lane & 3) * 2;
    #pragma unroll
    for (int mt = 0; mt < 2; mt++) {
        #pragma unroll
        for (int nt = 0; nt < 8; nt++) {
            float c0 = acc[mt][nt][0], c1 = acc[mt][nt][1];
            float c2 = acc[mt][nt][2], c3 = acc[mt][nt][3];
            if (act) {
                c0 = (c0 > 0.0f) ? (c0 + 1.0f) : expf(c0);
                c1 = (c1 > 0.0f) ? (c1 + 1.0f) : expf(c1);
                c2 = (c2 > 0.0f) ? (c2 + 1.0f) : expf(c2);
                c3 = (c3 > 0.0f) ? (c3 + 1.0f) : expf(c3);
            }
            const int r = row0 + mt * 16;
            const int cc = col0 + nt * 8;
            *(float2*)(C + (size_t)r * 512 + cc)       = make_float2(c0, c1);
            *(float2*)(C + (size_t)(r + 8) * 512 + cc) = make_float2(c2, c3);
        }
    }
}

// ---------------------------------------------------------------------------
// Stage 2a: per-(s-chunk, b, h) partial KV[d][dv] and Ksum[d]. Deterministic.
// ---------------------------------------------------------------------------
__global__ void kv_partial(const float* __restrict__ Kf,
                           const float* __restrict__ Vf,
                           float* __restrict__ part)
{
    const int c  = blockIdx.x;
    const int bh = blockIdx.y;
    const int b  = bh >> 4;
    const int h  = bh & 15;
    const int tid = threadIdx.x;

    __shared__ __align__(16) float Ks[8][32];
    __shared__ __align__(16) float Vs[8][32];

    const int d   = tid >> 3;
    const int dv0 = (tid & 7) << 2;
    const int lr  = tid >> 5;   // 0..7
    const int lc  = tid & 31;

    const size_t base = ((size_t)(b * L_ + c * (L_ / NCHUNK)) * 512) + h * 32;
    const float* Kb = Kf + base;
    const float* Vb = Vf + base;

    float a0 = 0.f, a1 = 0.f, a2 = 0.f, a3 = 0.f, ks = 0.f;

    for (int s = 0; s < L_ / NCHUNK; s += 8) {
        Ks[lr][lc] = Kb[(size_t)(s + lr) * 512 + lc];
        Vs[lr][lc] = Vb[(size_t)(s + lr) * 512 + lc];
        __syncthreads();
        #pragma unroll
        for (int u = 0; u < 8; u++) {
            float kd = Ks[u][d];
            float4 vv = *(const float4*)&Vs[u][dv0];
            a0 += kd * vv.x; a1 += kd * vv.y;
            a2 += kd * vv.z; a3 += kd * vv.w;
            ks += kd;
        }
        __syncthreads();
    }

    float* p = part + (size_t)c * PART_STRIDE;
    const int o = bh * 1024 + d * 32 + dv0;
    p[o + 0] = a0; p[o + 1] = a1; p[o + 2] = a2; p[o + 3] = a3;
    if ((tid & 7) == 0) p[KV_ELEMS + bh * 32 + d] = ks;
}

// Stage 2b: reduce NCHUNK partials -> g_KV, g_Ksum (deterministic order)
__global__ void kv_reduce(const float* __restrict__ part,
                          float* __restrict__ KV,
                          float* __restrict__ Ksum)
{
    const int i = blockIdx.x * 256 + threadIdx.x;
    if (i >= PART_STRIDE) return;
    float s = 0.f;
    #pragma unroll
    for (int c = 0; c < NCHUNK; c++) s += part[(size_t)c * PART_STRIDE + i];
    if (i < KV_ELEMS) KV[i] = s;
    else              Ksum[i - KV_ELEMS] = s;
}

// ---------------------------------------------------------------------------
// Z kernel: Z[l,h] = SC_ / (Q[l,h,:].Ksum[b,h] + eps). One thread per (l,h).
// ---------------------------------------------------------------------------
__global__ __launch_bounds__(256)
void zker(const float* __restrict__ Q, const float* __restrict__ Ksum,
          float* __restrict__ Z)
{
    const int idx = blockIdx.x * 256 + threadIdx.x;   // 0 .. ML*16-1
    const int l = idx >> 4, h = idx & 15;
    const int b = l >> 12;
    const float* Qp = Q + (size_t)l * 512 + h * 32;
    const float* Kp = Ksum + (b * 16 + h) * 32;
    float den = 0.f;
    #pragma unroll
    for (int d = 0; d < 32; d += 4) {
        float4 q4 = *(const float4*)(Qp + d);
        den += q4.x * Kp[d] + q4.y * Kp[d+1] + q4.z * Kp[d+2] + q4.w * Kp[d+3];
    }
    Z[idx] = SC_ / (den + EPS_);
}

// ---------------------------------------------------------------------------
// U build: U[b][e][32h+d] = (1/SC_) * sum_dv KV[b,h,d,dv] * Wm[e, 32h+dv]
// grid (B*H, 4): each block handles 128 e-rows for one (b,h).
// ---------------------------------------------------------------------------
__global__ __launch_bounds__(256)
void ubuild(const float* __restrict__ KV, const float* __restrict__ Wm,
            __half* __restrict__ U)
{
    const int bh = blockIdx.x;
    const int b = bh >> 4, h = bh & 15;
    const int tid = threadIdx.x;

    __shared__ __align__(16) float KVs[1024];
    for (int i = tid; i < 1024; i += 256) KVs[i] = KV[(size_t)bh * 1024 + i];
    __syncthreads();

    const int d0 = (tid & 7) * 4;
    const int eBase = blockIdx.y * 128;
    for (int e0 = eBase; e0 < eBase + 128; e0 += 32) {
        const int e = e0 + (tid >> 3);
        const float* wrow = Wm + (size_t)e * 512 + h * 32;
        float a0 = 0.f, a1 = 0.f, a2 = 0.f, a3 = 0.f;
        #pragma unroll 8
        for (int dv = 0; dv < 32; dv++) {
            float wv = wrow[dv];
            a0 += KVs[(d0 + 0) * 32 + dv] * wv;
            a1 += KVs[(d0 + 1) * 32 + dv] * wv;
            a2 += KVs[(d0 + 2) * 32 + dv] * wv;
            a3 += KVs[(d0 + 3) * 32 + dv] * wv;
        }
        const float is = 1.0f / SC_;
        __half2 p0 = __floats2half2_rn(a0 * is, a1 * is);
        __half2 p1 = __floats2half2_rn(a2 * is, a3 * is);
        __half* dst = U + ((size_t)b * 512 + e) * 512 + h * 32 + d0;
        *(__half2*)(dst)     = p0;
        *(__half2*)(dst + 2) = p1;
    }
}

// ---------------------------------------------------------------------------
// Launch. Inputs (metadata order): query, key, value, Wq, Wk, Wv, Wm. f32 out.
// ---------------------------------------------------------------------------
extern "C" void kernel_launch(void* const* d_in, const int* in_sizes, int n_in,
                              void* d_out, int out_size)
{
    (void)in_sizes; (void)n_in; (void)out_size;
    const float* q  = (const float*)d_in[0];
    const float* k  = (const float*)d_in[1];
    const float* v  = (const float*)d_in[2];
    const float* Wq = (const float*)d_in[3];
    const float* Wk = (const float*)d_in[4];
    const float* Wv = (const float*)d_in[5];
    const float* Wm = (const float*)d_in[6];
    float* out = (float*)d_out;

    float *gQ, *gK, *gV, *gPart, *gKV, *gKs, *gZ;
    __half *gWh, *gUh;
    cudaGetSymbolAddress((void**)&gQ,    g_Q);
    cudaGetSymbolAddress((void**)&gK,    g_K);
    cudaGetSymbolAddress((void**)&gV,    g_V);
    cudaGetSymbolAddress((void**)&gPart, g_part);
    cudaGetSymbolAddress((void**)&gKV,   g_KV);
    cudaGetSymbolAddress((void**)&gKs,   g_Ksum);
    cudaGetSymbolAddress((void**)&gZ,    g_Z);
    cudaGetSymbolAddress((void**)&gWh,   g_Wh);
    cudaGetSymbolAddress((void**)&gUh,   g_Uh);

    const int EE = E_ * E_;

    // 0) weights -> fp16 (once)
    wcvt<<<dim3(EE / 4 / 256, 3), 256>>>(Wq, Wk, Wv, gWh);

    // 1) fused projections: q,k -> elu+1 ; v -> raw
    {
        GemmArgs a;
        a.A[0] = q; a.W[0] = gWh + 0 * EE; a.C[0] = gQ;
        a.A[1] = k; a.W[1] = gWh + 1 * EE; a.C[1] = gK;
        a.A[2] = v; a.W[2] = gWh + 2 * EE; a.C[2] = gV;
        a.Zs = nullptr; a.actmask = 0x3; a.wPerBatch = 0;
        gemm_f16<<<dim3(4, 128, 3), 256>>>(a);
    }

    // 2) KV + Ksum (deterministic two-phase reduction)
    kv_partial<<<dim3(NCHUNK, B_ * H_), 256>>>(gK, gV, gPart);
    kv_reduce<<<(PART_STRIDE + 255) / 256, 256>>>(gPart, gKV, gKs);

    // 3) Z and fused U = KV @ Wm_head^T (per batch)
    zker<<<ML * H_ / 256, 256>>>(gQ, gKs, gZ);
    ubuild<<<dim3(B_ * H_, 4), 256>>>(gKV, Wm, gUh);

    // 4) fused message+merge GEMM: out = (Z*Q) @ U_b^T
    {
        GemmArgs a;
        a.A[0] = gQ; a.W[0] = gUh; a.C[0] = out;
        a.A[1] = gQ; a.W[1] = gUh; a.C[1] = out;
        a.A[2] = gQ; a.W[2] = gUh; a.C[2] = out;
        a.Zs = gZ; a.actmask = 0; a.wPerBatch = 1;
        gemm_f16<<<dim3(4, 128, 1), 256>>>(a);
    }
}

// round 13
// speedup vs baseline: 1.2949x; 1.0291x over previous
#include <cuda_runtime.h>
#include <cuda_fp16.h>
#include <math.h>
#include <stdint.h>

// Problem constants
#define B_  4
#define L_  4096
#define E_  512
#define H_  16
#define ML  (B_*L_)            // 16384 tokens
#define EPS_ 1e-6f
#define SC_  16384.0f          // z/U scale split (keeps fp16 ranges normal)

// ---------------------------------------------------------------------------
// Scratch (static __device__ arrays; no allocation anywhere)
// ---------------------------------------------------------------------------
__device__ __half g_Qh[ML*E_];    // elu(q)+1, fp16
__device__ __half g_Kh[ML*E_];    // elu(k)+1, fp16
__device__ __half g_Vh[ML*E_];    // v projection, fp16
__device__ __half g_Wh[3*E_*E_];  // Wq,Wk,Wv as fp16
__device__ __half g_Uh[B_*E_*E_]; // per-batch fused KV@Wm^T (scaled 1/SC_)
__device__ float g_Z[ML*H_];      // SC_ / (Q.Ksum + eps)

#define NCHUNK 16
#define KV_ELEMS   (B_*H_*32*32)     // 65536
#define KSUM_ELEMS (B_*H_*32)        // 2048
#define PART_STRIDE (KV_ELEMS + KSUM_ELEMS)   // 67584
__device__ float g_part[NCHUNK * PART_STRIDE];
__device__ float g_KV[KV_ELEMS];
__device__ float g_Ksum[KSUM_ELEMS];

// ---------------------------------------------------------------------------
// PTX helpers: ldmatrix + fp16 mma (fp32 accumulate)
// ---------------------------------------------------------------------------
__device__ __forceinline__ unsigned smem_u32(const void* p) {
    return (unsigned)__cvta_generic_to_shared(p);
}
__device__ __forceinline__ void ldsm_x4(unsigned* r, unsigned addr) {
    asm volatile("ldmatrix.sync.aligned.m8n8.x4.shared.b16 {%0,%1,%2,%3}, [%4];"
                 : "=r"(r[0]), "=r"(r[1]), "=r"(r[2]), "=r"(r[3]) : "r"(addr));
}
__device__ __forceinline__ void mma_f16(float* c, const unsigned* a, const unsigned* b) {
    asm volatile("mma.sync.aligned.m16n8k16.row.col.f32.f16.f16.f32 "
                 "{%0,%1,%2,%3}, {%4,%5,%6,%7}, {%8,%9}, {%0,%1,%2,%3};"
                 : "+f"(c[0]), "+f"(c[1]), "+f"(c[2]), "+f"(c[3])
                 : "r"(a[0]), "r"(a[1]), "r"(a[2]), "r"(a[3]),
                   "r"(b[0]), "r"(b[1]));
}

// 8 fp32 (optionally scaled) -> packed fp16 rn
__device__ __forceinline__ void cvt8_h(const float* __restrict__ v8, float s,
                                       uint4& h) {
    uint32_t hp[4];
    #pragma unroll
    for (int i = 0; i < 4; i++) {
        __half2 hh = __floats2half2_rn(v8[2*i] * s, v8[2*i+1] * s);
        hp[i] = *(uint32_t*)&hh;
    }
    h = make_uint4(hp[0], hp[1], hp[2], hp[3]);
}

// scale 8 packed fp16 by fp32 s (unpack -> mul -> repack; fp32 precision)
__device__ __forceinline__ uint4 scale8_h(uint4 u, float s) {
    uint32_t* p = (uint32_t*)&u;
    #pragma unroll
    for (int i = 0; i < 4; i++) {
        __half2 hh = *(__half2*)&p[i];
        float2 f = __half22float2(hh);
        __half2 r = __floats2half2_rn(f.x * s, f.y * s);
        p[i] = *(uint32_t*)&r;
    }
    return u;
}

// ---------------------------------------------------------------------------
// Weight pre-convert: fp32 -> fp16, 3 matrices (Wq, Wk, Wv)
// ---------------------------------------------------------------------------
__global__ void wcvt(const float* __restrict__ W0, const float* __restrict__ W1,
                     const float* __restrict__ W2, __half* __restrict__ out)
{
    const int z = blockIdx.y;
    const float* src = (z == 0) ? W0 : (z == 1 ? W1 : W2);
    int i = (blockIdx.x * 256 + threadIdx.x) * 4;
    float4 v = *(const float4*)(src + i);
    __half2 a = __floats2half2_rn(v.x, v.y);
    __half2 b = __floats2half2_rn(v.z, v.w);
    uint2 pk = make_uint2(*(uint32_t*)&a, *(uint32_t*)&b);
    *(uint2*)(out + (size_t)z * E_ * E_ + i) = pk;
}

// ---------------------------------------------------------------------------
// GEMM: C[M,N] = A[M,K] @ W[N,K]^T, fp16 mma, fp32 accum.
// AHALF: A already fp16 in gmem (staging = copy or copy+scale)
//        else fp32 A rn-quantized in staging.
// OUTHALF: C stored fp16 (projections) else fp32 (final output).
// Block 128x128, k-tile 32, 8 warps, warp tile 32x64, mma.m16n8k16,
// smem row stride 40 halves (conflict-free ldmatrix), register prefetch,
// single buffer + two barriers (measured-best schedule), 2 CTAs/SM.
// Optional Zs: per-(row, k-tile) scale folded into A staging. Optional
// per-batch W advance (merge GEMM uses per-batch U).
// ---------------------------------------------------------------------------
struct GemmArgs {
    const void* A[3]; const __half* W[3]; void* C[3];
    const float* Zs;    // null = no scaling; else Zs[row*16 + ktile]
    int actmask;
    int wPerBatch;      // W += 512*512 per 4096 A-rows
};

template<int AHALF, int OUTHALF>
__global__ __launch_bounds__(256, 2)
void gemm_f16(GemmArgs args)
{
    const int z = blockIdx.z;
    const bool act = (args.actmask >> z) & 1;

    const int m0 = blockIdx.y * 128;
    const int n0 = blockIdx.x * 128;

    const __half* Wb = args.W[z];
    if (args.wPerBatch) Wb += (size_t)(m0 >> 12) * (E_ * E_);

    __shared__ __half sAh[128 * 40];
    __shared__ __half sB [128 * 40];

    const int tid  = threadIdx.x;
    const int lane = tid & 31;
    const int warp = tid >> 5;
    const int wm0 = (warp & 3) * 32;     // warp row origin in tile
    const int wn0 = (warp >> 2) * 64;    // warp col origin in tile

    // global-load mapping: each thread owns one 16-elem row segment
    const int lrow = tid >> 1;           // 0..127
    const int lkc  = (tid & 1) * 16;     // k offset 0 or 16

    const float*  gAf = AHALF ? nullptr
                  : ((const float*)args.A[z] + (size_t)(m0 + lrow) * 512 + lkc);
    const __half* gAh = AHALF
                  ? ((const __half*)args.A[z] + (size_t)(m0 + lrow) * 512 + lkc)
                  : nullptr;
    const __half* gB = Wb + (size_t)(n0 + lrow) * 512 + lkc;
    const float*  Zrow = args.Zs ? (args.Zs + (size_t)(m0 + lrow) * 16) : nullptr;

    float acc[2][8][4];
    #pragma unroll
    for (int i = 0; i < 2; i++)
        #pragma unroll
        for (int j = 0; j < 8; j++)
            #pragma unroll
            for (int t = 0; t < 4; t++) acc[i][j][t] = 0.0f;

    const int sA0 = lrow * 40 + lkc;

    // ---- prologue: tile 0 ----
    float4 ra[4]; uint4 rha0, rha1; uint4 rb0, rb1; float zc;
    if (AHALF) {
        rha0 = *(const uint4*)(gAh);
        rha1 = *(const uint4*)(gAh + 8);
    } else {
        #pragma unroll
        for (int i = 0; i < 4; i++) ra[i] = *(const float4*)(gAf + 4 * i);
    }
    rb0 = *(const uint4*)(gB);
    rb1 = *(const uint4*)(gB + 8);
    zc = Zrow ? Zrow[0] : 1.0f;
    {
        uint4 h0, h1;
        if (AHALF) {
            h0 = Zrow ? scale8_h(rha0, zc) : rha0;
            h1 = Zrow ? scale8_h(rha1, zc) : rha1;
        } else {
            cvt8_h((const float*)&ra[0], zc, h0);
            cvt8_h((const float*)&ra[2], zc, h1);
        }
        *(uint4*)&sAh[sA0] = h0; *(uint4*)&sAh[sA0 + 8] = h1;
        *(uint4*)&sB[sA0] = rb0; *(uint4*)&sB[sA0 + 8] = rb1;
    }
    __syncthreads();

    // ldmatrix address components
    const int a_r = lane & 15;              // row within m16 tile
    const int a_c = (lane >> 4) * 8;        // col half
    const int b_r = lane & 7;               // row within n8 tile
    const int b_nt = (lane >> 4) & 1;       // which of 2 n-tiles in x4
    const int b_c = ((lane >> 3) & 1) * 8;  // col half

    for (int kt = 0; kt < 16; ++kt) {
        if (kt < 15) {
            const int ko = (kt + 1) * 32;
            if (AHALF) {
                rha0 = *(const uint4*)(gAh + ko);
                rha1 = *(const uint4*)(gAh + ko + 8);
            } else {
                #pragma unroll
                for (int i = 0; i < 4; i++) ra[i] = *(const float4*)(gAf + ko + 4 * i);
            }
            rb0 = *(const uint4*)(gB + ko);
            rb1 = *(const uint4*)(gB + ko + 8);
            zc = Zrow ? Zrow[kt + 1] : 1.0f;
        }

        #pragma unroll
        for (int ks = 0; ks < 2; ks++) {
            const int kk = ks * 16;
            unsigned ah[2][4];
            ldsm_x4(ah[0], smem_u32(&sAh[(wm0 + a_r) * 40 + kk + a_c]));
            ldsm_x4(ah[1], smem_u32(&sAh[(wm0 + 16 + a_r) * 40 + kk + a_c]));

            #pragma unroll
            for (int ntp = 0; ntp < 4; ntp++) {
                unsigned b[4];
                const int brow = wn0 + ntp * 16 + b_nt * 8 + b_r;
                ldsm_x4(b, smem_u32(&sB[brow * 40 + kk + b_c]));
                #pragma unroll
                for (int half = 0; half < 2; half++) {
                    const int nt = ntp * 2 + half;
                    const unsigned* bp = b + 2 * half;
                    mma_f16(acc[0][nt], ah[0], bp);
                    mma_f16(acc[1][nt], ah[1], bp);
                }
            }
        }

        if (kt < 15) {
            __syncthreads();
            uint4 h0, h1;
            if (AHALF) {
                h0 = Zrow ? scale8_h(rha0, zc) : rha0;
                h1 = Zrow ? scale8_h(rha1, zc) : rha1;
            } else {
                cvt8_h((const float*)&ra[0], zc, h0);
                cvt8_h((const float*)&ra[2], zc, h1);
            }
            *(uint4*)&sAh[sA0] = h0; *(uint4*)&sAh[sA0 + 8] = h1;
            *(uint4*)&sB[sA0] = rb0; *(uint4*)&sB[sA0 + 8] = rb1;
            __syncthreads();
        }
    }

    // ---- epilogue: optional elu(x)+1 (= x+1 if x>0 else exp(x)) ----
    const int row0 = m0 + wm0 + (lane >> 2);
    const int col0 = n0 + wn0 + (lane & 3) * 2;
    #pragma unroll
    for (int mt = 0; mt < 2; mt++) {
        #pragma unroll
        for (int nt = 0; nt < 8; nt++) {
            float c0 = acc[mt][nt][0], c1 = acc[mt][nt][1];
            float c2 = acc[mt][nt][2], c3 = acc[mt][nt][3];
            if (act) {
                c0 = (c0 > 0.0f) ? (c0 + 1.0f) : expf(c0);
                c1 = (c1 > 0.0f) ? (c1 + 1.0f) : expf(c1);
                c2 = (c2 > 0.0f) ? (c2 + 1.0f) : expf(c2);
                c3 = (c3 > 0.0f) ? (c3 + 1.0f) : expf(c3);
            }
            const int r = row0 + mt * 16;
            const int cc = col0 + nt * 8;
            if (OUTHALF) {
                __half* Cp = (__half*)args.C[z];
                __half2 p0 = __floats2half2_rn(c0, c1);
                __half2 p1 = __floats2half2_rn(c2, c3);
                *(__half2*)(Cp + (size_t)r * 512 + cc)       = p0;
                *(__half2*)(Cp + (size_t)(r + 8) * 512 + cc) = p1;
            } else {
                float* Cp = (float*)args.C[z];
                *(float2*)(Cp + (size_t)r * 512 + cc)       = make_float2(c0, c1);
                *(float2*)(Cp + (size_t)(r + 8) * 512 + cc) = make_float2(c2, c3);
            }
        }
    }
}

// ---------------------------------------------------------------------------
// Stage 2a: per-(s-chunk, b, h) partial KV[d][dv] and Ksum[d]. fp16 inputs,
// fp32 accumulation. Deterministic (no float atomics). NCHUNK=16.
// ---------------------------------------------------------------------------
__global__ void kv_partial(const __half* __restrict__ Kf,
                           const __half* __restrict__ Vf,
                           float* __restrict__ part)
{
    const int c  = blockIdx.x;
    const int bh = blockIdx.y;
    const int b  = bh >> 4;
    const int h  = bh & 15;
    const int tid = threadIdx.x;

    __shared__ __align__(16) float Ks[16][32];
    __shared__ __align__(16) float Vs[16][32];

    const int d   = tid >> 3;
    const int dv0 = (tid & 7) << 2;
    const int lr  = tid >> 4;          // 0..15
    const int lc  = (tid & 15) * 2;    // 0,2,..,30

    const size_t base = ((size_t)(b * L_ + c * (L_ / NCHUNK)) * 512) + h * 32;
    const __half* Kb = Kf + base;
    const __half* Vb = Vf + base;

    float a0 = 0.f, a1 = 0.f, a2 = 0.f, a3 = 0.f, ks = 0.f;

    for (int s = 0; s < L_ / NCHUNK; s += 16) {
        __half2 kk = *(const __half2*)(Kb + (size_t)(s + lr) * 512 + lc);
        __half2 vv2 = *(const __half2*)(Vb + (size_t)(s + lr) * 512 + lc);
        *(float2*)&Ks[lr][lc] = __half22float2(kk);
        *(float2*)&Vs[lr][lc] = __half22float2(vv2);
        __syncthreads();
        #pragma unroll
        for (int u = 0; u < 16; u++) {
            float kd = Ks[u][d];
            float4 vv = *(const float4*)&Vs[u][dv0];
            a0 += kd * vv.x; a1 += kd * vv.y;
            a2 += kd * vv.z; a3 += kd * vv.w;
            ks += kd;
        }
        __syncthreads();
    }

    float* p = part + (size_t)c * PART_STRIDE;
    const int o = bh * 1024 + d * 32 + dv0;
    p[o + 0] = a0; p[o + 1] = a1; p[o + 2] = a2; p[o + 3] = a3;
    if ((tid & 7) == 0) p[KV_ELEMS + bh * 32 + d] = ks;
}

// Stage 2b: reduce NCHUNK partials -> g_KV, g_Ksum (deterministic order)
__global__ void kv_reduce(const float* __restrict__ part,
                          float* __restrict__ KV,
                          float* __restrict__ Ksum)
{
    const int i = blockIdx.x * 256 + threadIdx.x;
    if (i >= PART_STRIDE) return;
    float s = 0.f;
    #pragma unroll
    for (int c = 0; c < NCHUNK; c++) s += part[(size_t)c * PART_STRIDE + i];
    if (i < KV_ELEMS) KV[i] = s;
    else              Ksum[i - KV_ELEMS] = s;
}

// ---------------------------------------------------------------------------
// Z kernel: Z[l,h] = SC_ / (Q[l,h,:].Ksum[b,h] + eps). One thread per (l,h).
// ---------------------------------------------------------------------------
__global__ __launch_bounds__(256)
void zker(const __half* __restrict__ Q, const float* __restrict__ Ksum,
          float* __restrict__ Z)
{
    const int idx = blockIdx.x * 256 + threadIdx.x;   // 0 .. ML*16-1
    const int l = idx >> 4, h = idx & 15;
    const int b = l >> 12;
    const __half2* Qp = (const __half2*)(Q + (size_t)l * 512 + h * 32);
    const float* Kp = Ksum + (b * 16 + h) * 32;
    float den = 0.f;
    #pragma unroll
    for (int d = 0; d < 16; d++) {
        float2 q2 = __half22float2(Qp[d]);
        den += q2.x * Kp[2*d] + q2.y * Kp[2*d + 1];
    }
    Z[idx] = SC_ / (den + EPS_);
}

// ---------------------------------------------------------------------------
// U build: U[b][e][32h+d] = (1/SC_) * sum_dv KV[b,h,d,dv] * Wm[e, 32h+dv]
// grid (B*H, 4): each block handles 128 e-rows for one (b,h).
// ---------------------------------------------------------------------------
__global__ __launch_bounds__(256)
void ubuild(const float* __restrict__ KV, const float* __restrict__ Wm,
            __half* __restrict__ U)
{
    const int bh = blockIdx.x;
    const int b = bh >> 4, h = bh & 15;
    const int tid = threadIdx.x;

    __shared__ __align__(16) float KVs[1024];
    for (int i = tid; i < 1024; i += 256) KVs[i] = KV[(size_t)bh * 1024 + i];
    __syncthreads();

    const int d0 = (tid & 7) * 4;
    const int eBase = blockIdx.y * 128;
    for (int e0 = eBase; e0 < eBase + 128; e0 += 32) {
        const int e = e0 + (tid >> 3);
        const float* wrow = Wm + (size_t)e * 512 + h * 32;
        float a0 = 0.f, a1 = 0.f, a2 = 0.f, a3 = 0.f;
        #pragma unroll 8
        for (int dv = 0; dv < 32; dv++) {
            float wv = wrow[dv];
            a0 += KVs[(d0 + 0) * 32 + dv] * wv;
            a1 += KVs[(d0 + 1) * 32 + dv] * wv;
            a2 += KVs[(d0 + 2) * 32 + dv] * wv;
            a3 += KVs[(d0 + 3) * 32 + dv] * wv;
        }
        const float is = 1.0f / SC_;
        __half2 p0 = __floats2half2_rn(a0 * is, a1 * is);
        __half2 p1 = __floats2half2_rn(a2 * is, a3 * is);
        __half* dst = U + ((size_t)b * 512 + e) * 512 + h * 32 + d0;
        *(__half2*)(dst)     = p0;
        *(__half2*)(dst + 2) = p1;
    }
}

// ---------------------------------------------------------------------------
// Launch. Inputs (metadata order): query, key, value, Wq, Wk, Wv, Wm. f32 out.
// ---------------------------------------------------------------------------
extern "C" void kernel_launch(void* const* d_in, const int* in_sizes, int n_in,
                              void* d_out, int out_size)
{
    (void)in_sizes; (void)n_in; (void)out_size;
    const float* q  = (const float*)d_in[0];
    const float* k  = (const float*)d_in[1];
    const float* v  = (const float*)d_in[2];
    const float* Wq = (const float*)d_in[3];
    const float* Wk = (const float*)d_in[4];
    const float* Wv = (const float*)d_in[5];
    const float* Wm = (const float*)d_in[6];
    float* out = (float*)d_out;

    float *gPart, *gKV, *gKs, *gZ;
    __half *gQh, *gKh, *gVh, *gWh, *gUh;
    cudaGetSymbolAddress((void**)&gQh,   g_Qh);
    cudaGetSymbolAddress((void**)&gKh,   g_Kh);
    cudaGetSymbolAddress((void**)&gVh,   g_Vh);
    cudaGetSymbolAddress((void**)&gPart, g_part);
    cudaGetSymbolAddress((void**)&gKV,   g_KV);
    cudaGetSymbolAddress((void**)&gKs,   g_Ksum);
    cudaGetSymbolAddress((void**)&gZ,    g_Z);
    cudaGetSymbolAddress((void**)&gWh,   g_Wh);
    cudaGetSymbolAddress((void**)&gUh,   g_Uh);

    const int EE = E_ * E_;

    // 0) weights -> fp16 (once)
    wcvt<<<dim3(EE / 4 / 256, 3), 256>>>(Wq, Wk, Wv, gWh);

    // 1) fused projections (fp16 out): q,k -> elu+1 ; v -> raw
    {
        GemmArgs a;
        a.A[0] = q; a.W[0] = gWh + 0 * EE; a.C[0] = gQh;
        a.A[1] = k; a.W[1] = gWh + 1 * EE; a.C[1] = gKh;
        a.A[2] = v; a.W[2] = gWh + 2 * EE; a.C[2] = gVh;
        a.Zs = nullptr; a.actmask = 0x3; a.wPerBatch = 0;
        gemm_f16<0, 1><<<dim3(4, 128, 3), 256>>>(a);
    }

    // 2) KV + Ksum (deterministic two-phase reduction, fp16 inputs)
    kv_partial<<<dim3(NCHUNK, B_ * H_), 256>>>(gKh, gVh, gPart);
    kv_reduce<<<(PART_STRIDE + 255) / 256, 256>>>(gPart, gKV, gKs);

    // 3) Z and fused U = KV @ Wm_head^T (per batch)
    zker<<<ML * H_ / 256, 256>>>(gQh, gKs, gZ);
    ubuild<<<dim3(B_ * H_, 4), 256>>>(gKV, Wm, gUh);

    // 4) fused message+merge GEMM: out = (Z*Q) @ U_b^T  (fp16 A, fp32 out)
    {
        GemmArgs a;
        a.A[0] = gQh; a.W[0] = gUh; a.C[0] = out;
        a.A[1] = gQh; a.W[1] = gUh; a.C[1] = out;
        a.A[2] = gQh; a.W[2] = gUh; a.C[2] = out;
        a.Zs = gZ; a.actmask = 0; a.wPerBatch = 1;
        gemm_f16<1, 0><<<dim3(4, 128, 1), 256>>>(a);
    }
}

// round 14
// speedup vs baseline: 1.4683x; 1.1339x over previous
#include <cuda_runtime.h>
#include <cuda_fp16.h>
#include <math.h>
#include <stdint.h>

// Problem constants
#define B_  4
#define L_  4096
#define E_  512
#define H_  16
#define ML  (B_*L_)            // 16384 tokens
#define EPS_ 1e-6f
#define SC_  16384.0f          // z/U scale split (keeps fp16 ranges normal)

// ---------------------------------------------------------------------------
// Scratch (static __device__ arrays; no allocation anywhere)
// ---------------------------------------------------------------------------
__device__ __half g_qi[ML*E_];    // fp16(query)
__device__ __half g_ki[ML*E_];    // fp16(key)
__device__ __half g_vi[ML*E_];    // fp16(value)
__device__ __half g_Qh[ML*E_];    // elu(q)+1 -> later scaled in place by z
__device__ __half g_Kh[ML*E_];    // elu(k)+1
__device__ __half g_Vh[ML*E_];    // v projection
__device__ __half g_Wh[3*E_*E_];  // Wq,Wk,Wv as fp16
__device__ __half g_Uh[B_*E_*E_]; // per-batch fused KV@Wm^T (scaled 1/SC_)

#define NCHUNK 16
#define KV_ELEMS   (B_*H_*32*32)     // 65536
#define KSUM_ELEMS (B_*H_*32)        // 2048
#define PART_STRIDE (KV_ELEMS + KSUM_ELEMS)   // 67584
__device__ float g_part[NCHUNK * PART_STRIDE];
__device__ float g_KV[KV_ELEMS];
__device__ float g_Ksum[KSUM_ELEMS];

// ---------------------------------------------------------------------------
// PTX helpers
// ---------------------------------------------------------------------------
__device__ __forceinline__ unsigned smem_u32(const void* p) {
    return (unsigned)__cvta_generic_to_shared(p);
}
__device__ __forceinline__ void ldsm_x4(unsigned* r, unsigned addr) {
    asm volatile("ldmatrix.sync.aligned.m8n8.x4.shared.b16 {%0,%1,%2,%3}, [%4];"
                 : "=r"(r[0]), "=r"(r[1]), "=r"(r[2]), "=r"(r[3]) : "r"(addr));
}
__device__ __forceinline__ void mma_f16(float* c, const unsigned* a, const unsigned* b) {
    asm volatile("mma.sync.aligned.m16n8k16.row.col.f32.f16.f16.f32 "
                 "{%0,%1,%2,%3}, {%4,%5,%6,%7}, {%8,%9}, {%0,%1,%2,%3};"
                 : "+f"(c[0]), "+f"(c[1]), "+f"(c[2]), "+f"(c[3])
                 : "r"(a[0]), "r"(a[1]), "r"(a[2]), "r"(a[3]),
                   "r"(b[0]), "r"(b[1]));
}
__device__ __forceinline__ void cpa16(uint32_t dst, const void* src) {
    asm volatile("cp.async.cg.shared.global [%0], [%1], 16;"
                 :: "r"(dst), "l"(src));
}
__device__ __forceinline__ void cpa_commit() {
    asm volatile("cp.async.commit_group;");
}
template<int N>
__device__ __forceinline__ void cpa_wait() {
    asm volatile("cp.async.wait_group %0;" :: "n"(N));
}

// ---------------------------------------------------------------------------
// fp32 -> fp16 convert kernels
// ---------------------------------------------------------------------------
__global__ void wcvt(const float* __restrict__ W0, const float* __restrict__ W1,
                     const float* __restrict__ W2, __half* __restrict__ out)
{
    const int z = blockIdx.y;
    const float* src = (z == 0) ? W0 : (z == 1 ? W1 : W2);
    int i = (blockIdx.x * 256 + threadIdx.x) * 4;
    float4 v = *(const float4*)(src + i);
    __half2 a = __floats2half2_rn(v.x, v.y);
    __half2 b = __floats2half2_rn(v.z, v.w);
    *(uint2*)(out + (size_t)z * E_ * E_ + i) =
        make_uint2(*(uint32_t*)&a, *(uint32_t*)&b);
}

__global__ void acvt(const float* __restrict__ A0, const float* __restrict__ A1,
                     const float* __restrict__ A2,
                     __half* __restrict__ O0, __half* __restrict__ O1,
                     __half* __restrict__ O2)
{
    const int z = blockIdx.y;
    const float* src = (z == 0) ? A0 : (z == 1 ? A1 : A2);
    __half* dst = (z == 0) ? O0 : (z == 1 ? O1 : O2);
    int i = (blockIdx.x * 256 + threadIdx.x) * 4;
    float4 v = *(const float4*)(src + i);
    __half2 a = __floats2half2_rn(v.x, v.y);
    __half2 b = __floats2half2_rn(v.z, v.w);
    *(uint2*)(dst + i) = make_uint2(*(uint32_t*)&a, *(uint32_t*)&b);
}

// ---------------------------------------------------------------------------
// GEMM: C[M,N] = A[M,K] @ W[N,K]^T, all operands fp16 in gmem, fp32 accum.
// cp.async 3-stage pipeline: staging is pure 16B async copies (no LDG->reg,
// no cvt, no STS in the hot loop), ONE barrier per k-tile, load latency
// covered by 2 tiles in flight. Block 128x128, k-tile 32, 8 warps, warp
// tile 32x64, mma.m16n8k16, smem row stride 40 halves (conflict-free
// ldmatrix). OUTHALF: fp16 C (projections) vs fp32 C (final output).
// ---------------------------------------------------------------------------
#define TILE_B   10240                 // one operand tile: 128*40 halves
#define STAGE_B  (2 * TILE_B)          // A + B
#define GSMEM    (3 * STAGE_B)         // 61440 B

struct GemmArgs {
    const __half* A[3]; const __half* W[3]; void* C[3];
    int actmask;
    int wPerBatch;      // W += 512*512 per 4096 A-rows
};

template<int OUTHALF>
__global__ __launch_bounds__(256, 2)
void gemm_f16(GemmArgs args)
{
    extern __shared__ char smem[];
    const int z = blockIdx.z;
    const bool act = (args.actmask >> z) & 1;

    const int m0 = blockIdx.y * 128;
    const int n0 = blockIdx.x * 128;

    const __half* Wb = args.W[z];
    if (args.wPerBatch) Wb += (size_t)(m0 >> 12) * (E_ * E_);

    const int tid  = threadIdx.x;
    const int lane = tid & 31;
    const int warp = tid >> 5;
    const int wm0 = (warp & 3) * 32;     // warp row origin in tile
    const int wn0 = (warp >> 2) * 64;    // warp col origin in tile

    // copy mapping: each thread owns one 16-half row segment (32B = 2x16B)
    const int lrow = tid >> 1;           // 0..127
    const int lkc  = (tid & 1) * 16;     // k offset 0 or 16

    const __half* gA = args.A[z] + (size_t)(m0 + lrow) * 512 + lkc;
    const __half* gB = Wb        + (size_t)(n0 + lrow) * 512 + lkc;

    const uint32_t sb = smem_u32(smem);
    const uint32_t dOfs = (uint32_t)(lrow * 40 + lkc) * 2;   // bytes

    float acc[2][8][4];
    #pragma unroll
    for (int i = 0; i < 2; i++)
        #pragma unroll
        for (int j = 0; j < 8; j++)
            #pragma unroll
            for (int t = 0; t < 4; t++) acc[i][j][t] = 0.0f;

    // issue one k-tile's copies into a stage
    auto issue = [&](int kt, int stage) {
        uint32_t dA = sb + stage * STAGE_B + dOfs;
        uint32_t dB = dA + TILE_B;
        const __half* sA = gA + kt * 32;
        const __half* sBp = gB + kt * 32;
        cpa16(dA,      sA);
        cpa16(dA + 16, sA + 8);
        cpa16(dB,      sBp);
        cpa16(dB + 16, sBp + 8);
        cpa_commit();
    };

    // ---- prologue: tiles 0,1 in flight ----
    issue(0, 0);
    issue(1, 1);

    // ldmatrix address components
    const int a_r = lane & 15;              // row within m16 tile
    const int a_c = (lane >> 4) * 8;        // col half
    const int b_r = lane & 7;               // row within n8 tile
    const int b_nt = (lane >> 4) & 1;       // which of 2 n-tiles in x4
    const int b_c = ((lane >> 3) & 1) * 8;  // col half

    for (int kt = 0; kt < 16; ++kt) {
        const int stage = kt % 3;
        if (kt == 15) cpa_wait<0>(); else cpa_wait<1>();   // tile kt landed
        __syncthreads();

        if (kt + 2 < 16) issue(kt + 2, (kt + 2) % 3);      // overwrites stage
                                                           // last read at kt-1
        const __half* sAh = (const __half*)(smem + stage * STAGE_B);
        const __half* sB  = (const __half*)(smem + stage * STAGE_B + TILE_B);

        #pragma unroll
        for (int ks = 0; ks < 2; ks++) {
            const int kk = ks * 16;
            unsigned ah[2][4];
            ldsm_x4(ah[0], smem_u32(&sAh[(wm0 + a_r) * 40 + kk + a_c]));
            ldsm_x4(ah[1], smem_u32(&sAh[(wm0 + 16 + a_r) * 40 + kk + a_c]));

            #pragma unroll
            for (int ntp = 0; ntp < 4; ntp++) {
                unsigned b[4];
                const int brow = wn0 + ntp * 16 + b_nt * 8 + b_r;
                ldsm_x4(b, smem_u32(&sB[brow * 40 + kk + b_c]));
                #pragma unroll
                for (int half = 0; half < 2; half++) {
                    const int nt = ntp * 2 + half;
                    const unsigned* bp = b + 2 * half;
                    mma_f16(acc[0][nt], ah[0], bp);
                    mma_f16(acc[1][nt], ah[1], bp);
                }
            }
        }
    }

    // ---- epilogue: optional elu(x)+1 (= x+1 if x>0 else exp(x)) ----
    const int row0 = m0 + wm0 + (lane >> 2);
    const int col0 = n0 + wn0 + (lane & 3) * 2;
    #pragma unroll
    for (int mt = 0; mt < 2; mt++) {
        #pragma unroll
        for (int nt = 0; nt < 8; nt++) {
            float c0 = acc[mt][nt][0], c1 = acc[mt][nt][1];
            float c2 = acc[mt][nt][2], c3 = acc[mt][nt][3];
            if (act) {
                c0 = (c0 > 0.0f) ? (c0 + 1.0f) : expf(c0);
                c1 = (c1 > 0.0f) ? (c1 + 1.0f) : expf(c1);
                c2 = (c2 > 0.0f) ? (c2 + 1.0f) : expf(c2);
                c3 = (c3 > 0.0f) ? (c3 + 1.0f) : expf(c3);
            }
            const int r = row0 + mt * 16;
            const int cc = col0 + nt * 8;
            if (OUTHALF) {
                __half* Cp = (__half*)args.C[z];
                __half2 p0 = __floats2half2_rn(c0, c1);
                __half2 p1 = __floats2half2_rn(c2, c3);
                *(__half2*)(Cp + (size_t)r * 512 + cc)       = p0;
                *(__half2*)(Cp + (size_t)(r + 8) * 512 + cc) = p1;
            } else {
                float* Cp = (float*)args.C[z];
                *(float2*)(Cp + (size_t)r * 512 + cc)       = make_float2(c0, c1);
                *(float2*)(Cp + (size_t)(r + 8) * 512 + cc) = make_float2(c2, c3);
            }
        }
    }
}

// ---------------------------------------------------------------------------
// Stage 2a: per-(s-chunk, b, h) partial KV[d][dv] and Ksum[d]. fp16 inputs,
// fp32 accumulation. Deterministic (no float atomics). NCHUNK=16.
// ---------------------------------------------------------------------------
__global__ void kv_partial(const __half* __restrict__ Kf,
                           const __half* __restrict__ Vf,
                           float* __restrict__ part)
{
    const int c  = blockIdx.x;
    const int bh = blockIdx.y;
    const int b  = bh >> 4;
    const int h  = bh & 15;
    const int tid = threadIdx.x;

    __shared__ __align__(16) float Ks[16][32];
    __shared__ __align__(16) float Vs[16][32];

    const int d   = tid >> 3;
    const int dv0 = (tid & 7) << 2;
    const int lr  = tid >> 4;          // 0..15
    const int lc  = (tid & 15) * 2;    // 0,2,..,30

    const size_t base = ((size_t)(b * L_ + c * (L_ / NCHUNK)) * 512) + h * 32;
    const __half* Kb = Kf + base;
    const __half* Vb = Vf + base;

    float a0 = 0.f, a1 = 0.f, a2 = 0.f, a3 = 0.f, ks = 0.f;

    for (int s = 0; s < L_ / NCHUNK; s += 16) {
        __half2 kk = *(const __half2*)(Kb + (size_t)(s + lr) * 512 + lc);
        __half2 vv2 = *(const __half2*)(Vb + (size_t)(s + lr) * 512 + lc);
        *(float2*)&Ks[lr][lc] = __half22float2(kk);
        *(float2*)&Vs[lr][lc] = __half22float2(vv2);
        __syncthreads();
        #pragma unroll
        for (int u = 0; u < 16; u++) {
            float kd = Ks[u][d];
            float4 vv = *(const float4*)&Vs[u][dv0];
            a0 += kd * vv.x; a1 += kd * vv.y;
            a2 += kd * vv.z; a3 += kd * vv.w;
            ks += kd;
        }
        __syncthreads();
    }

    float* p = part + (size_t)c * PART_STRIDE;
    const int o = bh * 1024 + d * 32 + dv0;
    p[o + 0] = a0; p[o + 1] = a1; p[o + 2] = a2; p[o + 3] = a3;
    if ((tid & 7) == 0) p[KV_ELEMS + bh * 32 + d] = ks;
}

// Stage 2b: reduce NCHUNK partials -> g_KV, g_Ksum (deterministic order)
__global__ void kv_reduce(const float* __restrict__ part,
                          float* __restrict__ KV,
                          float* __restrict__ Ksum)
{
    const int i = blockIdx.x * 256 + threadIdx.x;
    if (i >= PART_STRIDE) return;
    float s = 0.f;
    #pragma unroll
    for (int c = 0; c < NCHUNK; c++) s += part[(size_t)c * PART_STRIDE + i];
    if (i < KV_ELEMS) KV[i] = s;
    else              Ksum[i - KV_ELEMS] = s;
}

// ---------------------------------------------------------------------------
// zq: z = SC_/(Q.Ksum + eps); Q <- fp16(z * Q) IN PLACE (one thread per
// (l,h) row: each element read+written by exactly one thread -> safe).
// Identical rounding to the old per-k-tile scale in the merge GEMM.
// ---------------------------------------------------------------------------
__global__ __launch_bounds__(256)
void zq(__half* __restrict__ Q, const float* __restrict__ Ksum)
{
    const int idx = blockIdx.x * 256 + threadIdx.x;   // 0 .. ML*16-1
    const int l = idx >> 4, h = idx & 15;
    const int b = l >> 12;
    __half2* Qp = (__half2*)(Q + (size_t)l * 512 + h * 32);
    const float* Kp = Ksum + (b * 16 + h) * 32;

    float2 qf[16];
    float den = 0.f;
    #pragma unroll
    for (int d = 0; d < 16; d++) {
        qf[d] = __half22float2(Qp[d]);
        den += qf[d].x * Kp[2*d] + qf[d].y * Kp[2*d + 1];
    }
    const float zz = SC_ / (den + EPS_);
    #pragma unroll
    for (int d = 0; d < 16; d++)
        Qp[d] = __floats2half2_rn(qf[d].x * zz, qf[d].y * zz);
}

// ---------------------------------------------------------------------------
// U build: U[b][e][32h+d] = (1/SC_) * sum_dv KV[b,h,d,dv] * Wm[e, 32h+dv]
// grid (B*H, 4): each block handles 128 e-rows for one (b,h).
// ---------------------------------------------------------------------------
__global__ __launch_bounds__(256)
void ubuild(const float* __restrict__ KV, const float* __restrict__ Wm,
            __half* __restrict__ U)
{
    const int bh = blockIdx.x;
    const int b = bh >> 4, h = bh & 15;
    const int tid = threadIdx.x;

    __shared__ __align__(16) float KVs[1024];
    for (int i = tid; i < 1024; i += 256) KVs[i] = KV[(size_t)bh * 1024 + i];
    __syncthreads();

    const int d0 = (tid & 7) * 4;
    const int eBase = blockIdx.y * 128;
    for (int e0 = eBase; e0 < eBase + 128; e0 += 32) {
        const int e = e0 + (tid >> 3);
        const float* wrow = Wm + (size_t)e * 512 + h * 32;
        float a0 = 0.f, a1 = 0.f, a2 = 0.f, a3 = 0.f;
        #pragma unroll 8
        for (int dv = 0; dv < 32; dv++) {
            float wv = wrow[dv];
            a0 += KVs[(d0 + 0) * 32 + dv] * wv;
            a1 += KVs[(d0 + 1) * 32 + dv] * wv;
            a2 += KVs[(d0 + 2) * 32 + dv] * wv;
            a3 += KVs[(d0 + 3) * 32 + dv] * wv;
        }
        const float is = 1.0f / SC_;
        __half2 p0 = __floats2half2_rn(a0 * is, a1 * is);
        __half2 p1 = __floats2half2_rn(a2 * is, a3 * is);
        __half* dst = U + ((size_t)b * 512 + e) * 512 + h * 32 + d0;
        *(__half2*)(dst)     = p0;
        *(__half2*)(dst + 2) = p1;
    }
}

// ---------------------------------------------------------------------------
// Launch. Inputs (metadata order): query, key, value, Wq, Wk, Wv, Wm. f32 out.
// ---------------------------------------------------------------------------
extern "C" void kernel_launch(void* const* d_in, const int* in_sizes, int n_in,
                              void* d_out, int out_size)
{
    (void)in_sizes; (void)n_in; (void)out_size;
    const float* q  = (const float*)d_in[0];
    const float* k  = (const float*)d_in[1];
    const float* v  = (const float*)d_in[2];
    const float* Wq = (const float*)d_in[3];
    const float* Wk = (const float*)d_in[4];
    const float* Wv = (const float*)d_in[5];
    const float* Wm = (const float*)d_in[6];
    float* out = (float*)d_out;

    float *gPart, *gKV, *gKs;
    __half *gqi, *gki, *gvi, *gQh, *gKh, *gVh, *gWh, *gUh;
    cudaGetSymbolAddress((void**)&gqi,   g_qi);
    cudaGetSymbolAddress((void**)&gki,   g_ki);
    cudaGetSymbolAddress((void**)&gvi,   g_vi);
    cudaGetSymbolAddress((void**)&gQh,   g_Qh);
    cudaGetSymbolAddress((void**)&gKh,   g_Kh);
    cudaGetSymbolAddress((void**)&gVh,   g_Vh);
    cudaGetSymbolAddress((void**)&gPart, g_part);
    cudaGetSymbolAddress((void**)&gKV,   g_KV);
    cudaGetSymbolAddress((void**)&gKs,   g_Ksum);
    cudaGetSymbolAddress((void**)&gWh,   g_Wh);
    cudaGetSymbolAddress((void**)&gUh,   g_Uh);

    cudaFuncSetAttribute(gemm_f16<1>,
        cudaFuncAttributeMaxDynamicSharedMemorySize, GSMEM);
    cudaFuncSetAttribute(gemm_f16<0>,
        cudaFuncAttributeMaxDynamicSharedMemorySize, GSMEM);

    const int EE = E_ * E_;

    // 0) weights + activations -> fp16 (once)
    wcvt<<<dim3(EE / 4 / 256, 3), 256>>>(Wq, Wk, Wv, gWh);
    acvt<<<dim3(ML * E_ / 4 / 256, 3), 256>>>(q, k, v, gqi, gki, gvi);

    // 1) fused projections (fp16 in/out, cp.async pipeline): q,k -> elu+1
    {
        GemmArgs a;
        a.A[0] = gqi; a.W[0] = gWh + 0 * EE; a.C[0] = gQh;
        a.A[1] = gki; a.W[1] = gWh + 1 * EE; a.C[1] = gKh;
        a.A[2] = gvi; a.W[2] = gWh + 2 * EE; a.C[2] = gVh;
        a.actmask = 0x3; a.wPerBatch = 0;
        gemm_f16<1><<<dim3(4, 128, 3), 256, GSMEM>>>(a);
    }

    // 2) KV + Ksum (deterministic two-phase reduction, fp16 inputs)
    kv_partial<<<dim3(NCHUNK, B_ * H_), 256>>>(gKh, gVh, gPart);
    kv_reduce<<<(PART_STRIDE + 255) / 256, 256>>>(gPart, gKV, gKs);

    // 3) fold z into Q (in place) and build fused U = KV @ Wm_head^T
    zq<<<ML * H_ / 256, 256>>>(gQh, gKs);
    ubuild<<<dim3(B_ * H_, 4), 256>>>(gKV, Wm, gUh);

    // 4) fused message+merge GEMM: out = (zQ) @ U_b^T  (fp32 out)
    {
        GemmArgs a;
        a.A[0] = gQh; a.W[0] = gUh; a.C[0] = out;
        a.A[1] = gQh; a.W[1] = gUh; a.C[1] = out;
        a.A[2] = gQh; a.W[2] = gUh; a.C[2] = out;
        a.actmask = 0; a.wPerBatch = 1;
        gemm_f16<0><<<dim3(4, 128, 1), 256, GSMEM>>>(a);
    }
}

// round 15
// speedup vs baseline: 1.6375x; 1.1153x over previous
#include <cuda_runtime.h>
#include <cuda_fp16.h>
#include <math.h>
#include <stdint.h>

// Problem constants
#define B_  4
#define L_  4096
#define E_  512
#define H_  16
#define ML  (B_*L_)            // 16384 tokens
#define EPS_ 1e-6f
#define SC_  16384.0f          // z/U scale split (keeps fp16 ranges normal)

// ---------------------------------------------------------------------------
// Scratch (static __device__ arrays; no allocation anywhere)
// ---------------------------------------------------------------------------
__device__ __half g_qi[ML*E_];    // fp16(query)
__device__ __half g_ki[ML*E_];    // fp16(key)
__device__ __half g_vi[ML*E_];    // fp16(value)
__device__ __half g_Qh[ML*E_];    // elu(q)+1 -> later scaled in place by z
__device__ __half g_Kh[ML*E_];    // elu(k)+1
__device__ __half g_Vh[ML*E_];    // v projection
__device__ __half g_Wh[3*E_*E_];  // Wq,Wk,Wv as fp16
__device__ __half g_Uh[B_*E_*E_]; // per-batch fused KV@Wm^T (scaled 1/SC_)

#define NCHUNK 16
#define KV_ELEMS   (B_*H_*32*32)     // 65536
#define KSUM_ELEMS (B_*H_*32)        // 2048
#define PART_STRIDE (KV_ELEMS + KSUM_ELEMS)   // 67584
__device__ float g_part[NCHUNK * PART_STRIDE];
__device__ float g_KV[KV_ELEMS];
__device__ float g_Ksum[KSUM_ELEMS];

// ---------------------------------------------------------------------------
// PTX helpers
// ---------------------------------------------------------------------------
__device__ __forceinline__ unsigned smem_u32(const void* p) {
    return (unsigned)__cvta_generic_to_shared(p);
}
__device__ __forceinline__ void ldsm_x4(unsigned* r, unsigned addr) {
    asm volatile("ldmatrix.sync.aligned.m8n8.x4.shared.b16 {%0,%1,%2,%3}, [%4];"
                 : "=r"(r[0]), "=r"(r[1]), "=r"(r[2]), "=r"(r[3]) : "r"(addr));
}
__device__ __forceinline__ void ldsm_x4t(unsigned* r, unsigned addr) {
    asm volatile("ldmatrix.sync.aligned.m8n8.x4.trans.shared.b16 {%0,%1,%2,%3}, [%4];"
                 : "=r"(r[0]), "=r"(r[1]), "=r"(r[2]), "=r"(r[3]) : "r"(addr));
}
__device__ __forceinline__ void mma_f16(float* c, const unsigned* a, const unsigned* b) {
    asm volatile("mma.sync.aligned.m16n8k16.row.col.f32.f16.f16.f32 "
                 "{%0,%1,%2,%3}, {%4,%5,%6,%7}, {%8,%9}, {%0,%1,%2,%3};"
                 : "+f"(c[0]), "+f"(c[1]), "+f"(c[2]), "+f"(c[3])
                 : "r"(a[0]), "r"(a[1]), "r"(a[2]), "r"(a[3]),
                   "r"(b[0]), "r"(b[1]));
}
__device__ __forceinline__ void cpa16(uint32_t dst, const void* src) {
    asm volatile("cp.async.cg.shared.global [%0], [%1], 16;"
                 :: "r"(dst), "l"(src));
}
__device__ __forceinline__ void cpa_commit() {
    asm volatile("cp.async.commit_group;");
}
template<int N>
__device__ __forceinline__ void cpa_wait() {
    asm volatile("cp.async.wait_group %0;" :: "n"(N));
}

// ---------------------------------------------------------------------------
// fp32 -> fp16 convert kernels
// ---------------------------------------------------------------------------
__global__ void wcvt(const float* __restrict__ W0, const float* __restrict__ W1,
                     const float* __restrict__ W2, __half* __restrict__ out)
{
    const int z = blockIdx.y;
    const float* src = (z == 0) ? W0 : (z == 1 ? W1 : W2);
    int i = (blockIdx.x * 256 + threadIdx.x) * 4;
    float4 v = *(const float4*)(src + i);
    __half2 a = __floats2half2_rn(v.x, v.y);
    __half2 b = __floats2half2_rn(v.z, v.w);
    *(uint2*)(out + (size_t)z * E_ * E_ + i) =
        make_uint2(*(uint32_t*)&a, *(uint32_t*)&b);
}

__global__ void acvt(const float* __restrict__ A0, const float* __restrict__ A1,
                     const float* __restrict__ A2,
                     __half* __restrict__ O0, __half* __restrict__ O1,
                     __half* __restrict__ O2)
{
    const int z = blockIdx.y;
    const float* src = (z == 0) ? A0 : (z == 1 ? A1 : A2);
    __half* dst = (z == 0) ? O0 : (z == 1 ? O1 : O2);
    int i = (blockIdx.x * 256 + threadIdx.x) * 4;
    float4 v = *(const float4*)(src + i);
    __half2 a = __floats2half2_rn(v.x, v.y);
    __half2 b = __floats2half2_rn(v.z, v.w);
    *(uint2*)(dst + i) = make_uint2(*(uint32_t*)&a, *(uint32_t*)&b);
}

// ---------------------------------------------------------------------------
// GEMM: C[M,N] = A[M,K] @ W[N,K]^T, all operands fp16 in gmem, fp32 accum.
// cp.async 3-stage pipeline, ONE barrier per k-tile. Block 128x128, k-tile
// 32, 8 warps, warp tile 32x64, mma.m16n8k16, smem row stride 40 halves.
// OUTHALF: fp16 C (projections) vs fp32 C (final output).
// ---------------------------------------------------------------------------
#define TILE_B   10240                 // one operand tile: 128*40 halves
#define STAGE_B  (2 * TILE_B)          // A + B
#define GSMEM    (3 * STAGE_B)         // 61440 B

struct GemmArgs {
    const __half* A[3]; const __half* W[3]; void* C[3];
    int actmask;
    int wPerBatch;      // W += 512*512 per 4096 A-rows
};

template<int OUTHALF>
__global__ __launch_bounds__(256, 2)
void gemm_f16(GemmArgs args)
{
    extern __shared__ char smem[];
    const int z = blockIdx.z;
    const bool act = (args.actmask >> z) & 1;

    const int m0 = blockIdx.y * 128;
    const int n0 = blockIdx.x * 128;

    const __half* Wb = args.W[z];
    if (args.wPerBatch) Wb += (size_t)(m0 >> 12) * (E_ * E_);

    const int tid  = threadIdx.x;
    const int lane = tid & 31;
    const int warp = tid >> 5;
    const int wm0 = (warp & 3) * 32;     // warp row origin in tile
    const int wn0 = (warp >> 2) * 64;    // warp col origin in tile

    // copy mapping: each thread owns one 16-half row segment (32B = 2x16B)
    const int lrow = tid >> 1;           // 0..127
    const int lkc  = (tid & 1) * 16;     // k offset 0 or 16

    const __half* gA = args.A[z] + (size_t)(m0 + lrow) * 512 + lkc;
    const __half* gB = Wb        + (size_t)(n0 + lrow) * 512 + lkc;

    const uint32_t sb = smem_u32(smem);
    const uint32_t dOfs = (uint32_t)(lrow * 40 + lkc) * 2;   // bytes

    float acc[2][8][4];
    #pragma unroll
    for (int i = 0; i < 2; i++)
        #pragma unroll
        for (int j = 0; j < 8; j++)
            #pragma unroll
            for (int t = 0; t < 4; t++) acc[i][j][t] = 0.0f;

    auto issue = [&](int kt, int stage) {
        uint32_t dA = sb + stage * STAGE_B + dOfs;
        uint32_t dB = dA + TILE_B;
        const __half* sA = gA + kt * 32;
        const __half* sBp = gB + kt * 32;
        cpa16(dA,      sA);
        cpa16(dA + 16, sA + 8);
        cpa16(dB,      sBp);
        cpa16(dB + 16, sBp + 8);
        cpa_commit();
    };

    issue(0, 0);
    issue(1, 1);

    const int a_r = lane & 15;
    const int a_c = (lane >> 4) * 8;
    const int b_r = lane & 7;
    const int b_nt = (lane >> 4) & 1;
    const int b_c = ((lane >> 3) & 1) * 8;

    for (int kt = 0; kt < 16; ++kt) {
        const int stage = kt % 3;
        if (kt == 15) cpa_wait<0>(); else cpa_wait<1>();
        __syncthreads();

        if (kt + 2 < 16) issue(kt + 2, (kt + 2) % 3);

        const __half* sAh = (const __half*)(smem + stage * STAGE_B);
        const __half* sB  = (const __half*)(smem + stage * STAGE_B + TILE_B);

        #pragma unroll
        for (int ks = 0; ks < 2; ks++) {
            const int kk = ks * 16;
            unsigned ah[2][4];
            ldsm_x4(ah[0], smem_u32(&sAh[(wm0 + a_r) * 40 + kk + a_c]));
            ldsm_x4(ah[1], smem_u32(&sAh[(wm0 + 16 + a_r) * 40 + kk + a_c]));

            #pragma unroll
            for (int ntp = 0; ntp < 4; ntp++) {
                unsigned b[4];
                const int brow = wn0 + ntp * 16 + b_nt * 8 + b_r;
                ldsm_x4(b, smem_u32(&sB[brow * 40 + kk + b_c]));
                #pragma unroll
                for (int half = 0; half < 2; half++) {
                    const int nt = ntp * 2 + half;
                    const unsigned* bp = b + 2 * half;
                    mma_f16(acc[0][nt], ah[0], bp);
                    mma_f16(acc[1][nt], ah[1], bp);
                }
            }
        }
    }

    // ---- epilogue ----
    const int row0 = m0 + wm0 + (lane >> 2);
    const int col0 = n0 + wn0 + (lane & 3) * 2;
    #pragma unroll
    for (int mt = 0; mt < 2; mt++) {
        #pragma unroll
        for (int nt = 0; nt < 8; nt++) {
            float c0 = acc[mt][nt][0], c1 = acc[mt][nt][1];
            float c2 = acc[mt][nt][2], c3 = acc[mt][nt][3];
            if (act) {
                c0 = (c0 > 0.0f) ? (c0 + 1.0f) : expf(c0);
                c1 = (c1 > 0.0f) ? (c1 + 1.0f) : expf(c1);
                c2 = (c2 > 0.0f) ? (c2 + 1.0f) : expf(c2);
                c3 = (c3 > 0.0f) ? (c3 + 1.0f) : expf(c3);
            }
            const int r = row0 + mt * 16;
            const int cc = col0 + nt * 8;
            if (OUTHALF) {
                __half* Cp = (__half*)args.C[z];
                __half2 p0 = __floats2half2_rn(c0, c1);
                __half2 p1 = __floats2half2_rn(c2, c3);
                *(__half2*)(Cp + (size_t)r * 512 + cc)       = p0;
                *(__half2*)(Cp + (size_t)(r + 8) * 512 + cc) = p1;
            } else {
                float* Cp = (float*)args.C[z];
                *(float2*)(Cp + (size_t)r * 512 + cc)       = make_float2(c0, c1);
                *(float2*)(Cp + (size_t)(r + 8) * 512 + cc) = make_float2(c2, c3);
            }
        }
    }
}

// ---------------------------------------------------------------------------
// Stage 2a on TENSOR CORES: per-(chunk, b, h) partial
//   KV[d][dv] = sum_s K[s,d]*V[s,dv]   and   Ksum[d] = sum_s K[s,d]
// A = K^T via ldmatrix.trans, B = V via ldmatrix.trans, mma.m16n8k16 fp32
// accum (same products/accumulator as the scalar version). Ksum comes from
// one extra mma per A-tile against a constant B = 1.0 fragment (column 0).
// Per warp: 2 s-steps of 16; smem tiles stride 40 halves (conflict-free
// ldmatrix, same pattern as the GEMM). 8-warp deterministic smem reduction.
// ---------------------------------------------------------------------------
__global__ __launch_bounds__(256)
void kv_mma(const __half* __restrict__ Kf, const __half* __restrict__ Vf,
            float* __restrict__ part)
{
    __shared__ __align__(16) char smem[8 * 1056 * 4];  // 33792 B (red buffer)
    const int c  = blockIdx.x;
    const int bh = blockIdx.y;
    const int b  = bh >> 4;
    const int h  = bh & 15;
    const int tid  = threadIdx.x;
    const int warp = tid >> 5;
    const int lane = tid & 31;
    const int li   = lane & 7;

    // per-warp tiles: K at warp*2560B, V at +1280B (16 rows x 40 halves each)
    __half* sK = (__half*)(smem) + warp * 1280;
    __half* sV = sK + 640;

    float acc[2][4][4];
    float ksa[2][4];
    #pragma unroll
    for (int mt = 0; mt < 2; mt++) {
        #pragma unroll
        for (int nt = 0; nt < 4; nt++)
            #pragma unroll
            for (int t = 0; t < 4; t++) acc[mt][nt][t] = 0.0f;
        #pragma unroll
        for (int t = 0; t < 4; t++) ksa[mt][t] = 0.0f;
    }
    const unsigned bone[2] = {0x3C003C00u, 0x3C003C00u};   // fp16 1.0 x4

    const size_t base = ((size_t)(b * L_ + c * (L_ / NCHUNK)) * 512) + h * 32;

    // staging mapping: lane -> (row = lane>>1, 16-half segment = (lane&1)*16)
    const int srow = lane >> 1;
    const int scol = (lane & 1) * 16;

    // ldmatrix address components (derived from m16n8k16 fragment layouts)
    const int aRow = ((lane >> 4) & 1) * 8 + li;   // A: quadrant s-row
    const int aCol = ((lane >> 3) & 1) * 8;        // A: quadrant d-col
    const int vRow = ((lane >> 3) & 1) * 8 + li;   // B: quadrant s-row
    const int vCol = ((lane >> 4) & 1) * 8;        // B: quadrant dv-col

    for (int step = warp; step < 16; step += 8) {
        const __half* Kp = Kf + base + (size_t)step * 16 * 512;
        const __half* Vp = Vf + base + (size_t)step * 16 * 512;

        __syncwarp();
        *(uint4*)&sK[srow * 40 + scol]     = *(const uint4*)(Kp + (size_t)srow * 512 + scol);
        *(uint4*)&sK[srow * 40 + scol + 8] = *(const uint4*)(Kp + (size_t)srow * 512 + scol + 8);
        *(uint4*)&sV[srow * 40 + scol]     = *(const uint4*)(Vp + (size_t)srow * 512 + scol);
        *(uint4*)&sV[srow * 40 + scol + 8] = *(const uint4*)(Vp + (size_t)srow * 512 + scol + 8);
        __syncwarp();

        unsigned a[2][4], bv[2][4];
        ldsm_x4t(a[0], smem_u32(&sK[aRow * 40 + 0  + aCol]));   // d 0-15
        ldsm_x4t(a[1], smem_u32(&sK[aRow * 40 + 16 + aCol]));   // d 16-31
        ldsm_x4t(bv[0], smem_u32(&sV[vRow * 40 + 0  + vCol]));  // dv 0-15
        ldsm_x4t(bv[1], smem_u32(&sV[vRow * 40 + 16 + vCol]));  // dv 16-31

        #pragma unroll
        for (int mt = 0; mt < 2; mt++) {
            mma_f16(acc[mt][0], a[mt], bv[0]);
            mma_f16(acc[mt][1], a[mt], bv[0] + 2);
            mma_f16(acc[mt][2], a[mt], bv[1]);
            mma_f16(acc[mt][3], a[mt], bv[1] + 2);
            mma_f16(ksa[mt],    a[mt], bone);
        }
    }
    __syncthreads();   // tiles no longer needed; smem becomes red buffer

    // per-warp results -> smem (fragment scatter, layout d*32+dv)
    float* red = (float*)smem + warp * 1056;
    const int dr = lane >> 2;
    const int dc = (lane & 3) * 2;
    #pragma unroll
    for (int mt = 0; mt < 2; mt++) {
        #pragma unroll
        for (int nt = 0; nt < 4; nt++) {
            red[(mt*16 + dr)     * 32 + nt*8 + dc]     = acc[mt][nt][0];
            red[(mt*16 + dr)     * 32 + nt*8 + dc + 1] = acc[mt][nt][1];
            red[(mt*16 + dr + 8) * 32 + nt*8 + dc]     = acc[mt][nt][2];
            red[(mt*16 + dr + 8) * 32 + nt*8 + dc + 1] = acc[mt][nt][3];
        }
        if ((lane & 3) == 0) {
            red[1024 + mt*16 + dr]     = ksa[mt][0];
            red[1024 + mt*16 + dr + 8] = ksa[mt][2];
        }
    }
    __syncthreads();

    // deterministic 8-warp reduction -> g_part (same layout as before)
    float* p = part + (size_t)c * PART_STRIDE;
    const float* rbase = (const float*)smem;
    for (int i = tid; i < 1056; i += 256) {
        float s = 0.f;
        #pragma unroll
        for (int w = 0; w < 8; w++) s += rbase[w * 1056 + i];
        if (i < 1024) p[bh * 1024 + i] = s;
        else          p[KV_ELEMS + bh * 32 + (i - 1024)] = s;
    }
}

// Stage 2b: reduce NCHUNK partials -> g_KV, g_Ksum (deterministic order)
__global__ void kv_reduce(const float* __restrict__ part,
                          float* __restrict__ KV,
                          float* __restrict__ Ksum)
{
    const int i = blockIdx.x * 256 + threadIdx.x;
    if (i >= PART_STRIDE) return;
    float s = 0.f;
    #pragma unroll
    for (int c = 0; c < NCHUNK; c++) s += part[(size_t)c * PART_STRIDE + i];
    if (i < KV_ELEMS) KV[i] = s;
    else              Ksum[i - KV_ELEMS] = s;
}

// ---------------------------------------------------------------------------
// zq: z = SC_/(Q.Ksum + eps); Q <- fp16(z * Q) IN PLACE.
// ---------------------------------------------------------------------------
__global__ __launch_bounds__(256)
void zq(__half* __restrict__ Q, const float* __restrict__ Ksum)
{
    const int idx = blockIdx.x * 256 + threadIdx.x;   // 0 .. ML*16-1
    const int l = idx >> 4, h = idx & 15;
    const int b = l >> 12;
    __half2* Qp = (__half2*)(Q + (size_t)l * 512 + h * 32);
    const float* Kp = Ksum + (b * 16 + h) * 32;

    float2 qf[16];
    float den = 0.f;
    #pragma unroll
    for (int d = 0; d < 16; d++) {
        qf[d] = __half22float2(Qp[d]);
        den += qf[d].x * Kp[2*d] + qf[d].y * Kp[2*d + 1];
    }
    const float zz = SC_ / (den + EPS_);
    #pragma unroll
    for (int d = 0; d < 16; d++)
        Qp[d] = __floats2half2_rn(qf[d].x * zz, qf[d].y * zz);
}

// ---------------------------------------------------------------------------
// U build: U[b][e][32h+d] = (1/SC_) * sum_dv KV[b,h,d,dv] * Wm[e, 32h+dv]
// ---------------------------------------------------------------------------
__global__ __launch_bounds__(256)
void ubuild(const float* __restrict__ KV, const float* __restrict__ Wm,
            __half* __restrict__ U)
{
    const int bh = blockIdx.x;
    const int b = bh >> 4, h = bh & 15;
    const int tid = threadIdx.x;

    __shared__ __align__(16) float KVs[1024];
    for (int i = tid; i < 1024; i += 256) KVs[i] = KV[(size_t)bh * 1024 + i];
    __syncthreads();

    const int d0 = (tid & 7) * 4;
    const int eBase = blockIdx.y * 128;
    for (int e0 = eBase; e0 < eBase + 128; e0 += 32) {
        const int e = e0 + (tid >> 3);
        const float* wrow = Wm + (size_t)e * 512 + h * 32;
        float a0 = 0.f, a1 = 0.f, a2 = 0.f, a3 = 0.f;
        #pragma unroll 8
        for (int dv = 0; dv < 32; dv++) {
            float wv = wrow[dv];
            a0 += KVs[(d0 + 0) * 32 + dv] * wv;
            a1 += KVs[(d0 + 1) * 32 + dv] * wv;
            a2 += KVs[(d0 + 2) * 32 + dv] * wv;
            a3 += KVs[(d0 + 3) * 32 + dv] * wv;
        }
        const float is = 1.0f / SC_;
        __half2 p0 = __floats2half2_rn(a0 * is, a1 * is);
        __half2 p1 = __floats2half2_rn(a2 * is, a3 * is);
        __half* dst = U + ((size_t)b * 512 + e) * 512 + h * 32 + d0;
        *(__half2*)(dst)     = p0;
        *(__half2*)(dst + 2) = p1;
    }
}

// ---------------------------------------------------------------------------
// Launch. Inputs (metadata order): query, key, value, Wq, Wk, Wv, Wm. f32 out.
// ---------------------------------------------------------------------------
extern "C" void kernel_launch(void* const* d_in, const int* in_sizes, int n_in,
                              void* d_out, int out_size)
{
    (void)in_sizes; (void)n_in; (void)out_size;
    const float* q  = (const float*)d_in[0];
    const float* k  = (const float*)d_in[1];
    const float* v  = (const float*)d_in[2];
    const float* Wq = (const float*)d_in[3];
    const float* Wk = (const float*)d_in[4];
    const float* Wv = (const float*)d_in[5];
    const float* Wm = (const float*)d_in[6];
    float* out = (float*)d_out;

    float *gPart, *gKV, *gKs;
    __half *gqi, *gki, *gvi, *gQh, *gKh, *gVh, *gWh, *gUh;
    cudaGetSymbolAddress((void**)&gqi,   g_qi);
    cudaGetSymbolAddress((void**)&gki,   g_ki);
    cudaGetSymbolAddress((void**)&gvi,   g_vi);
    cudaGetSymbolAddress((void**)&gQh,   g_Qh);
    cudaGetSymbolAddress((void**)&gKh,   g_Kh);
    cudaGetSymbolAddress((void**)&gVh,   g_Vh);
    cudaGetSymbolAddress((void**)&gPart, g_part);
    cudaGetSymbolAddress((void**)&gKV,   g_KV);
    cudaGetSymbolAddress((void**)&gKs,   g_Ksum);
    cudaGetSymbolAddress((void**)&gWh,   g_Wh);
    cudaGetSymbolAddress((void**)&gUh,   g_Uh);

    cudaFuncSetAttribute(gemm_f16<1>,
        cudaFuncAttributeMaxDynamicSharedMemorySize, GSMEM);
    cudaFuncSetAttribute(gemm_f16<0>,
        cudaFuncAttributeMaxDynamicSharedMemorySize, GSMEM);

    const int EE = E_ * E_;

    // 0) weights + activations -> fp16 (once)
    wcvt<<<dim3(EE / 4 / 256, 3), 256>>>(Wq, Wk, Wv, gWh);
    acvt<<<dim3(ML * E_ / 4 / 256, 3), 256>>>(q, k, v, gqi, gki, gvi);

    // 1) fused projections (fp16 in/out, cp.async pipeline): q,k -> elu+1
    {
        GemmArgs a;
        a.A[0] = gqi; a.W[0] = gWh + 0 * EE; a.C[0] = gQh;
        a.A[1] = gki; a.W[1] = gWh + 1 * EE; a.C[1] = gKh;
        a.A[2] = gvi; a.W[2] = gWh + 2 * EE; a.C[2] = gVh;
        a.actmask = 0x3; a.wPerBatch = 0;
        gemm_f16<1><<<dim3(4, 128, 3), 256, GSMEM>>>(a);
    }

    // 2) KV + Ksum on tensor cores (deterministic two-phase reduction)
    kv_mma<<<dim3(NCHUNK, B_ * H_), 256>>>(gKh, gVh, gPart);
    kv_reduce<<<(PART_STRIDE + 255) / 256, 256>>>(gPart, gKV, gKs);

    // 3) fold z into Q (in place) and build fused U = KV @ Wm_head^T
    zq<<<ML * H_ / 256, 256>>>(gQh, gKs);
    ubuild<<<dim3(B_ * H_, 4), 256>>>(gKV, Wm, gUh);

    // 4) fused message+merge GEMM: out = (zQ) @ U_b^T  (fp32 out)
    {
        GemmArgs a;
        a.A[0] = gQh; a.W[0] = gUh; a.C[0] = out;
        a.A[1] = gQh; a.W[1] = gUh; a.C[1] = out;
        a.A[2] = gQh; a.W[2] = gUh; a.C[2] = out;
        a.actmask = 0; a.wPerBatch = 1;
        gemm_f16<0><<<dim3(4, 128, 1), 256, GSMEM>>>(a);
    }
}